// round 1
// baseline (speedup 1.0000x reference)
#include <cuda_runtime.h>

// ---------------- problem constants ----------------
namespace {
constexpr int kB   = 8;
constexpr int kC   = 256;
constexpr int kN   = 4096;      // H*W
constexpr int kC3  = 768;
constexpr int kFFN = 2048;
constexpr int kHD  = 64;        // head dim
constexpr int kBH  = 32;        // B * heads
constexpr int kNCH = 16;        // n-chunks for split-K attention S
}

// ---------------- scratch (device globals; no allocs allowed) ----------------
__device__ float g_xln[kB * kN * kC];           // LN1 output, (B,N,C)
__device__ float g_qkv[kB * kN * kC3];          // QKV, (B,N,3C)
__device__ float g_spart[kBH * kNCH * kHD * kHD]; // partial S
__device__ float g_attn[kBH * kHD * kHD];       // softmaxed attn, stored [e][dd] (transposed)
__device__ float g_attnout[kB * kN * kC];       // attention output, (B,N,C)
__device__ float g_proj[kB * kN * kC];          // proj output, (B,N,C)
__device__ float g_ln2[kB * kN * kC];           // LN2 output
__device__ float g_ffh[kB * kN * kFFN];         // FFN hidden
__device__ float g_ffo[kB * kN * kC];           // FFN2 output

// ---------------- LN1: (B,C,N) -> LN over C -> (B,N,C) ----------------
__global__ __launch_bounds__(256) void ln1_kernel(const float* __restrict__ x,
                                                  const float* __restrict__ g1,
                                                  const float* __restrict__ be1)
{
    __shared__ float s[32][257];
    __shared__ float smu[32], srs[32];
    int b  = blockIdx.y;
    int n0 = blockIdx.x * 32;
    int tid = threadIdx.x;
    const float* xb = x + (size_t)b * kC * kN;

    // load 32 pixels x 256 channels, transposing via shared
    #pragma unroll
    for (int it = 0; it < 32; ++it) {
        int idx = it * 256 + tid;
        int c = idx >> 5, nn = idx & 31;
        s[nn][c] = xb[(size_t)c * kN + n0 + nn];
    }
    __syncthreads();

    // per-pixel mean/var: 8 threads per pixel
    int nn = tid >> 3, g = tid & 7;
    float sum = 0.f, sq = 0.f;
    #pragma unroll
    for (int j = 0; j < 32; ++j) {
        float v = s[nn][g + j * 8];
        sum += v; sq += v * v;
    }
    sum += __shfl_xor_sync(0xffffffffu, sum, 1, 8);
    sum += __shfl_xor_sync(0xffffffffu, sum, 2, 8);
    sum += __shfl_xor_sync(0xffffffffu, sum, 4, 8);
    sq  += __shfl_xor_sync(0xffffffffu, sq, 1, 8);
    sq  += __shfl_xor_sync(0xffffffffu, sq, 2, 8);
    sq  += __shfl_xor_sync(0xffffffffu, sq, 4, 8);
    if (g == 0) {
        float mu = sum * (1.f / 256.f);
        float var = sq * (1.f / 256.f) - mu * mu;
        smu[nn] = mu;
        srs[nn] = rsqrtf(var + 1e-5f);
    }
    __syncthreads();

    float gg = g1[tid], bb = be1[tid];
    float* yb = g_xln + ((size_t)b * kN + n0) * kC;
    #pragma unroll
    for (int it = 0; it < 32; ++it) {
        float mu = smu[it], rs = srs[it];
        yb[(size_t)it * kC + tid] = (s[it][tid] - mu) * rs * gg + bb;
    }
}

// ---------------- SGEMM: Y[m][o] = act(sum_k A[m][k] * W[o][k] + bias[o]) ----------------
// A: MxK row-major, W: OxK row-major, Y: MxO row-major.
// 128x128 tile, K-tile 8, 256 threads, 8x8 per thread, reg prefetch.
// Requires M%128==0, O%128==0, K%8==0.
template <bool RELU>
__global__ __launch_bounds__(256, 2) void sgemm_nt(const float* __restrict__ A,
                                                   const float* __restrict__ W,
                                                   const float* __restrict__ bias,
                                                   float* __restrict__ Y,
                                                   int M, int O, int K)
{
    __shared__ float As[8][132];
    __shared__ float Ws[8][132];
    int tid = threadIdx.x;
    int bm = blockIdx.y * 128;
    int bo = blockIdx.x * 128;
    int lr = tid >> 1;            // 0..127 tile row
    int lk = (tid & 1) << 2;      // 0 or 4
    const float* Ap = A + (size_t)(bm + lr) * K + lk;
    const float* Wp = W + (size_t)(bo + lr) * K + lk;
    int tx = tid & 15, ty = tid >> 4;

    float acc[8][8];
    #pragma unroll
    for (int i = 0; i < 8; ++i)
        #pragma unroll
        for (int j = 0; j < 8; ++j) acc[i][j] = 0.f;

    float4 ra = *(const float4*)Ap;
    float4 rw = *(const float4*)Wp;
    int kt = K >> 3;
    for (int t = 0; t < kt; ++t) {
        As[lk + 0][lr] = ra.x; As[lk + 1][lr] = ra.y;
        As[lk + 2][lr] = ra.z; As[lk + 3][lr] = ra.w;
        Ws[lk + 0][lr] = rw.x; Ws[lk + 1][lr] = rw.y;
        Ws[lk + 2][lr] = rw.z; Ws[lk + 3][lr] = rw.w;
        __syncthreads();
        if (t + 1 < kt) {
            ra = *(const float4*)(Ap + (size_t)(t + 1) * 8);
            rw = *(const float4*)(Wp + (size_t)(t + 1) * 8);
        }
        #pragma unroll
        for (int k = 0; k < 8; ++k) {
            float a0[8], w0[8];
            *(float4*)(a0)     = *(const float4*)(&As[k][ty * 8]);
            *(float4*)(a0 + 4) = *(const float4*)(&As[k][ty * 8 + 4]);
            *(float4*)(w0)     = *(const float4*)(&Ws[k][tx * 8]);
            *(float4*)(w0 + 4) = *(const float4*)(&Ws[k][tx * 8 + 4]);
            #pragma unroll
            for (int i = 0; i < 8; ++i)
                #pragma unroll
                for (int j = 0; j < 8; ++j)
                    acc[i][j] += a0[i] * w0[j];
        }
        __syncthreads();
    }

    float bv[8];
    #pragma unroll
    for (int j = 0; j < 8; ++j) bv[j] = bias[bo + tx * 8 + j];

    #pragma unroll
    for (int i = 0; i < 8; ++i) {
        float* yp = Y + (size_t)(bm + ty * 8 + i) * O + bo + tx * 8;
        float v[8];
        #pragma unroll
        for (int j = 0; j < 8; ++j) {
            v[j] = acc[i][j] + bv[j];
            if (RELU) v[j] = fmaxf(v[j], 0.f);
        }
        float4 o0 = {v[0], v[1], v[2], v[3]};
        float4 o1 = {v[4], v[5], v[6], v[7]};
        *(float4*)yp       = o0;
        *(float4*)(yp + 4) = o1;
    }
}

// ---------------- attention: S partial = (Q/8) . K^T, contracted over n-chunk ----------------
__global__ __launch_bounds__(256) void attn_s_kernel()
{
    int bh = blockIdx.x;              // 0..31
    int ch = blockIdx.y;              // 0..15
    int b = bh >> 2, h = bh & 3;
    __shared__ float Qs[32][68];
    __shared__ float Ks[32][68];
    int tid = threadIdx.x;
    int tx = tid & 15, ty = tid >> 4;
    float acc[4][4] = {};
    const float* base = g_qkv + (size_t)b * kN * kC3 + h * kHD;
    int n0 = ch * 256;

    for (int nt = 0; nt < 8; ++nt) {
        int n1 = n0 + nt * 32;
        #pragma unroll
        for (int r = 0; r < 2; ++r) {
            int idx = r * 256 + tid;
            int nn = idx >> 4;
            int e4 = (idx & 15) << 2;
            const float* p = base + (size_t)(n1 + nn) * kC3 + e4;
            float4 q  = *(const float4*)p;
            float4 kv = *(const float4*)(p + kC);   // k part lives +256 in the row
            Qs[nn][e4 + 0] = q.x * 0.125f; Qs[nn][e4 + 1] = q.y * 0.125f;
            Qs[nn][e4 + 2] = q.z * 0.125f; Qs[nn][e4 + 3] = q.w * 0.125f;
            Ks[nn][e4 + 0] = kv.x; Ks[nn][e4 + 1] = kv.y;
            Ks[nn][e4 + 2] = kv.z; Ks[nn][e4 + 3] = kv.w;
        }
        __syncthreads();
        #pragma unroll 8
        for (int nn = 0; nn < 32; ++nn) {
            float qf[4], kf[4];
            *(float4*)qf = *(const float4*)&Qs[nn][ty * 4];
            *(float4*)kf = *(const float4*)&Ks[nn][tx * 4];
            #pragma unroll
            for (int i = 0; i < 4; ++i)
                #pragma unroll
                for (int j = 0; j < 4; ++j)
                    acc[i][j] += qf[i] * kf[j];
        }
        __syncthreads();
    }
    float* sp = g_spart + (size_t)(bh * kNCH + ch) * kHD * kHD;
    #pragma unroll
    for (int i = 0; i < 4; ++i)
        #pragma unroll
        for (int j = 0; j < 4; ++j)
            sp[(ty * 4 + i) * kHD + tx * 4 + j] = acc[i][j];
}

// ---------------- softmax over attn rows; reduce split-K partials; store transposed ----------------
__global__ __launch_bounds__(256) void softmax_kernel()
{
    int bh  = blockIdx.x;
    int tid = threadIdx.x;
    int dd  = tid >> 2;               // attn row (query channel idx)
    int f0  = (tid & 3) << 4;         // 16 cols per thread
    float v[16];
    #pragma unroll
    for (int j = 0; j < 16; ++j) v[j] = 0.f;
    for (int p = 0; p < kNCH; ++p) {
        const float* sp = g_spart + ((size_t)(bh * kNCH + p) * kHD + dd) * kHD + f0;
        #pragma unroll
        for (int j = 0; j < 16; ++j) v[j] += sp[j];
    }
    float m = v[0];
    #pragma unroll
    for (int j = 1; j < 16; ++j) m = fmaxf(m, v[j]);
    m = fmaxf(m, __shfl_xor_sync(0xffffffffu, m, 1, 4));
    m = fmaxf(m, __shfl_xor_sync(0xffffffffu, m, 2, 4));
    float s = 0.f;
    #pragma unroll
    for (int j = 0; j < 16; ++j) { v[j] = expf(v[j] - m); s += v[j]; }
    s += __shfl_xor_sync(0xffffffffu, s, 1, 4);
    s += __shfl_xor_sync(0xffffffffu, s, 2, 4);
    float inv = 1.f / s;
    float* at = g_attn + (size_t)bh * kHD * kHD;
    #pragma unroll
    for (int j = 0; j < 16; ++j)
        at[(f0 + j) * kHD + dd] = v[j] * inv;    // store [e][dd]
}

// ---------------- attn @ V -> attnout (B,N,C) ----------------
__global__ __launch_bounds__(256) void attn_av_kernel()
{
    int bh = blockIdx.y;
    int b = bh >> 2, h = bh & 3;
    int n0 = blockIdx.x * 64;
    __shared__ float Vs[64][68];   // [n_local][e]
    __shared__ float At[64][68];   // [e][dd]
    int tid = threadIdx.x;
    const float* vbase = g_qkv + (size_t)b * kN * kC3 + 2 * kC + h * kHD;
    const float* abase = g_attn + (size_t)bh * kHD * kHD;
    #pragma unroll
    for (int r = 0; r < 4; ++r) {
        int idx = r * 256 + tid;            // 0..1023
        int nn = idx >> 4;
        int e4 = (idx & 15) << 2;
        *(float4*)&Vs[nn][e4] = *(const float4*)(vbase + (size_t)(n0 + nn) * kC3 + e4);
        *(float4*)&At[nn][e4] = *(const float4*)(abase + nn * kHD + e4);
    }
    __syncthreads();
    int tx = tid & 15, ty = tid >> 4;
    float acc[4][4] = {};
    #pragma unroll 4
    for (int e = 0; e < 64; ++e) {
        float va[4], at[4];
        va[0] = Vs[ty * 4 + 0][e];
        va[1] = Vs[ty * 4 + 1][e];
        va[2] = Vs[ty * 4 + 2][e];
        va[3] = Vs[ty * 4 + 3][e];
        *(float4*)at = *(const float4*)&At[e][tx * 4];
        #pragma unroll
        for (int i = 0; i < 4; ++i)
            #pragma unroll
            for (int j = 0; j < 4; ++j)
                acc[i][j] += va[i] * at[j];
    }
    float* yb = g_attnout + ((size_t)b * kN + n0) * kC + h * kHD + tx * 4;
    #pragma unroll
    for (int i = 0; i < 4; ++i) {
        float4 o = {acc[i][0], acc[i][1], acc[i][2], acc[i][3]};
        *(float4*)(yb + (size_t)(ty * 4 + i) * kC) = o;
    }
}

// ---------------- LN2 over rows of g_proj ----------------
__global__ __launch_bounds__(256) void ln2_kernel(const float* __restrict__ g2,
                                                  const float* __restrict__ be2)
{
    int row  = blockIdx.x * 8 + (threadIdx.x >> 5);
    int lane = threadIdx.x & 31;
    const float* p = g_proj + (size_t)row * kC;
    float4 a = *(const float4*)(p + lane * 4);
    float4 c = *(const float4*)(p + 128 + lane * 4);
    float s = a.x + a.y + a.z + a.w + c.x + c.y + c.z + c.w;
    float q = a.x * a.x + a.y * a.y + a.z * a.z + a.w * a.w
            + c.x * c.x + c.y * c.y + c.z * c.z + c.w * c.w;
    #pragma unroll
    for (int off = 16; off; off >>= 1) {
        s += __shfl_xor_sync(0xffffffffu, s, off);
        q += __shfl_xor_sync(0xffffffffu, q, off);
    }
    float mu = s * (1.f / 256.f);
    float rs = rsqrtf(q * (1.f / 256.f) - mu * mu + 1e-5f);
    int c0 = lane * 4, c1 = 128 + lane * 4;
    float* o = g_ln2 + (size_t)row * kC;
    float4 o0, o1;
    o0.x = (a.x - mu) * rs * g2[c0 + 0] + be2[c0 + 0];
    o0.y = (a.y - mu) * rs * g2[c0 + 1] + be2[c0 + 1];
    o0.z = (a.z - mu) * rs * g2[c0 + 2] + be2[c0 + 2];
    o0.w = (a.w - mu) * rs * g2[c0 + 3] + be2[c0 + 3];
    o1.x = (c.x - mu) * rs * g2[c1 + 0] + be2[c1 + 0];
    o1.y = (c.y - mu) * rs * g2[c1 + 1] + be2[c1 + 1];
    o1.z = (c.z - mu) * rs * g2[c1 + 2] + be2[c1 + 2];
    o1.w = (c.w - mu) * rs * g2[c1 + 3] + be2[c1 + 3];
    *(float4*)(o + c0) = o0;
    *(float4*)(o + c1) = o1;
}

// ---------------- transpose (B,N,C)->(B,C,N) + residual ----------------
__global__ __launch_bounds__(256) void resid_kernel(const float* __restrict__ x,
                                                    float* __restrict__ out)
{
    int b = blockIdx.z, c0 = blockIdx.y * 32, n0 = blockIdx.x * 32;
    __shared__ float s[32][33];
    int tid = threadIdx.x;
    const float* fb = g_ffo + ((size_t)b * kN + n0) * kC + c0;
    #pragma unroll
    for (int r = 0; r < 4; ++r) {
        int idx = r * 256 + tid;
        int nn = idx >> 5, cc = idx & 31;
        s[nn][cc] = fb[(size_t)nn * kC + cc];
    }
    __syncthreads();
    const float* xb = x + ((size_t)b * kC + c0) * kN + n0;
    float* ob = out + ((size_t)b * kC + c0) * kN + n0;
    #pragma unroll
    for (int r = 0; r < 4; ++r) {
        int idx = r * 256 + tid;
        int cc = idx >> 5, nn = idx & 31;
        ob[(size_t)cc * kN + nn] = s[nn][cc] + xb[(size_t)cc * kN + nn];
    }
}

// ---------------- launch ----------------
extern "C" void kernel_launch(void* const* d_in, const int* in_sizes, int n_in,
                              void* d_out, int out_size)
{
    const float* x      = (const float*)d_in[0];
    const float* w_qkv  = (const float*)d_in[1];
    const float* b_qkv  = (const float*)d_in[2];
    const float* w_proj = (const float*)d_in[3];
    const float* b_proj = (const float*)d_in[4];
    const float* w_ffn1 = (const float*)d_in[5];
    const float* b_ffn1 = (const float*)d_in[6];
    const float* w_ffn2 = (const float*)d_in[7];
    const float* b_ffn2 = (const float*)d_in[8];
    const float* g1     = (const float*)d_in[9];
    const float* be1    = (const float*)d_in[10];
    const float* g2     = (const float*)d_in[11];
    const float* be2    = (const float*)d_in[12];
    float* out = (float*)d_out;

    void *p_xln, *p_qkv, *p_attnout, *p_proj, *p_ln2, *p_ffh, *p_ffo;
    cudaGetSymbolAddress(&p_xln, g_xln);
    cudaGetSymbolAddress(&p_qkv, g_qkv);
    cudaGetSymbolAddress(&p_attnout, g_attnout);
    cudaGetSymbolAddress(&p_proj, g_proj);
    cudaGetSymbolAddress(&p_ln2, g_ln2);
    cudaGetSymbolAddress(&p_ffh, g_ffh);
    cudaGetSymbolAddress(&p_ffo, g_ffo);

    const int M = kB * kN;  // 32768

    ln1_kernel<<<dim3(kN / 32, kB), 256>>>(x, g1, be1);

    sgemm_nt<false><<<dim3(kC3 / 128, M / 128), 256>>>(
        (const float*)p_xln, w_qkv, b_qkv, (float*)p_qkv, M, kC3, kC);

    attn_s_kernel<<<dim3(kBH, kNCH), 256>>>();
    softmax_kernel<<<kBH, 256>>>();
    attn_av_kernel<<<dim3(kN / 64, kBH), 256>>>();

    sgemm_nt<false><<<dim3(kC / 128, M / 128), 256>>>(
        (const float*)p_attnout, w_proj, b_proj, (float*)p_proj, M, kC, kC);

    ln2_kernel<<<M / 8, 256>>>(g2, be2);

    sgemm_nt<true><<<dim3(kFFN / 128, M / 128), 256>>>(
        (const float*)p_ln2, w_ffn1, b_ffn1, (float*)p_ffh, M, kFFN, kC);

    sgemm_nt<false><<<dim3(kC / 128, M / 128), 256>>>(
        (const float*)p_ffh, w_ffn2, b_ffn2, (float*)p_ffo, M, kC, kFFN);

    resid_kernel<<<dim3(kN / 32, kC / 32, kB), 256>>>(x, out);
}

// round 3
// speedup vs baseline: 2.2401x; 2.2401x over previous
#include <cuda_runtime.h>
#include <cstdint>

// ---------------- problem constants ----------------
namespace {
constexpr int kB   = 8;
constexpr int kC   = 256;
constexpr int kN   = 4096;
constexpr int kC3  = 768;
constexpr int kFFN = 2048;
constexpr int kHD  = 64;
constexpr int kBH  = 32;
constexpr int kNCH = 16;

constexpr int PADW   = 36;                 // padded row stride in words (conflict-free frags)
constexpr int TILEB  = 128 * PADW * 4;     // 18432 bytes per operand tile
constexpr int STAGEB = 2 * TILEB;          // 36864 bytes per stage (A+B)
constexpr int NSTG   = 4;
constexpr uint32_t SMEM_DYN = STAGEB * NSTG; // 147456
}

// ---------------- scratch ----------------
__device__ float g_xln[kB * kN * kC];
__device__ float g_qkv[kB * kN * kC3];
__device__ float g_spart[kBH * kNCH * kHD * kHD];
__device__ float g_attn[kBH * kHD * kHD];
__device__ float g_attnout[kB * kN * kC];
__device__ float g_proj[kB * kN * kC];
__device__ float g_ln2[kB * kN * kC];
__device__ float g_ffh[kB * kN * kFFN];
__device__ float g_ffo[kB * kN * kC];

// ---------------- helpers ----------------
__device__ __forceinline__ uint32_t smem_u32(const void* p) {
    uint32_t a;
    asm("{ .reg .u64 t; cvta.to.shared.u64 t, %1; cvt.u32.u64 %0, t; }" : "=r"(a) : "l"(p));
    return a;
}
__device__ __forceinline__ void cp_async16(uint32_t s, const void* g) {
    asm volatile("cp.async.cg.shared.global [%0], [%1], 16;" :: "r"(s), "l"(g));
}
#define CP_COMMIT() asm volatile("cp.async.commit_group;" ::: "memory")
#define CP_WAIT2()  asm volatile("cp.async.wait_group 2;" ::: "memory")
#define CP_WAIT0()  asm volatile("cp.async.wait_group 0;" ::: "memory")

__device__ __forceinline__ void mma_tf32(float& c0, float& c1, float& c2, float& c3,
                                         uint32_t a0, uint32_t a1, uint32_t a2, uint32_t a3,
                                         uint32_t b0, uint32_t b1) {
    asm volatile(
        "mma.sync.aligned.m16n8k8.row.col.f32.tf32.tf32.f32 "
        "{%0,%1,%2,%3}, {%4,%5,%6,%7}, {%8,%9}, {%0,%1,%2,%3};"
        : "+f"(c0), "+f"(c1), "+f"(c2), "+f"(c3)
        : "r"(a0), "r"(a1), "r"(a2), "r"(a3), "r"(b0), "r"(b1));
}

// ---------------- LN1: (B,C,N) -> LN over C -> (B,N,C) ----------------
__global__ __launch_bounds__(256) void ln1_kernel(const float* __restrict__ x,
                                                  const float* __restrict__ g1,
                                                  const float* __restrict__ be1)
{
    __shared__ float s[32][257];
    __shared__ float smu[32], srs[32];
    int b  = blockIdx.y;
    int n0 = blockIdx.x * 32;
    int tid = threadIdx.x;
    const float* xb = x + (size_t)b * kC * kN;
    #pragma unroll
    for (int it = 0; it < 32; ++it) {
        int idx = it * 256 + tid;
        int c = idx >> 5, nn = idx & 31;
        s[nn][c] = xb[(size_t)c * kN + n0 + nn];
    }
    __syncthreads();
    int nn = tid >> 3, g = tid & 7;
    float sum = 0.f, sq = 0.f;
    #pragma unroll
    for (int j = 0; j < 32; ++j) { float v = s[nn][g + j * 8]; sum += v; sq += v * v; }
    sum += __shfl_xor_sync(0xffffffffu, sum, 1, 8);
    sum += __shfl_xor_sync(0xffffffffu, sum, 2, 8);
    sum += __shfl_xor_sync(0xffffffffu, sum, 4, 8);
    sq  += __shfl_xor_sync(0xffffffffu, sq, 1, 8);
    sq  += __shfl_xor_sync(0xffffffffu, sq, 2, 8);
    sq  += __shfl_xor_sync(0xffffffffu, sq, 4, 8);
    if (g == 0) {
        float mu = sum * (1.f / 256.f);
        smu[nn] = mu;
        srs[nn] = rsqrtf(sq * (1.f / 256.f) - mu * mu + 1e-5f);
    }
    __syncthreads();
    float gg = g1[tid], bb = be1[tid];
    float* yb = g_xln + ((size_t)b * kN + n0) * kC;
    #pragma unroll
    for (int it = 0; it < 32; ++it)
        yb[(size_t)it * kC + tid] = (s[it][tid] - smu[it]) * srs[it] * gg + bb;
}

// ---------------- tensor-core GEMM (mma.sync tf32), tile 128x128x32 ----------------
// A: MxK row-major; W: OxK row-major; Y[m][o] = act(sum A*W + bias).
// 256 threads = 8 warps in 4(M) x 2(N) grid; warp tile 32x64 (2 m-frags x 8 n-frags).
template <bool RELU>
__global__ __launch_bounds__(256) void gemm_mma(const float* __restrict__ A,
                                                const float* __restrict__ W,
                                                const float* __restrict__ bias,
                                                float* __restrict__ Y,
                                                int K, int O)
{
    extern __shared__ __align__(16) char smem[];
    const uint32_t sbase = smem_u32(smem);
    const int tid = threadIdx.x;
    const int lane = tid & 31;
    const int wid = tid >> 5;
    const int g  = lane >> 2;      // 0..7
    const int t4 = lane & 3;       // 0..3
    const int wm = wid >> 1;       // 0..3
    const int wn = wid & 1;        // 0..1
    const int m0 = blockIdx.y * 128;
    const int n0 = blockIdx.x * 128;
    const int NC = K >> 5;

    const int r_ld = tid >> 3;     // 0..31
    const int c_ld = tid & 7;      // 16B chunk

    float acc[2][8][4];
    #pragma unroll
    for (int i = 0; i < 2; ++i)
        #pragma unroll
        for (int j = 0; j < 8; ++j)
            #pragma unroll
            for (int r = 0; r < 4; ++r) acc[i][j][r] = 0.f;

    auto load_stage = [&](int t) {
        const uint32_t sA = sbase + (t & (NSTG - 1)) * STAGEB;
        const uint32_t sB = sA + TILEB;
        const int k0 = t * 32;
        const float* Ag = A + (size_t)(m0 + r_ld) * K + k0 + c_ld * 4;
        const float* Wg = W + (size_t)(n0 + r_ld) * K + k0 + c_ld * 4;
        #pragma unroll
        for (int p = 0; p < 4; ++p) {
            cp_async16(sA + (p * 32 + r_ld) * (PADW * 4) + c_ld * 16, Ag + (size_t)(p * 32) * K);
            cp_async16(sB + (p * 32 + r_ld) * (PADW * 4) + c_ld * 16, Wg + (size_t)(p * 32) * K);
        }
    };

    #pragma unroll
    for (int t = 0; t < NSTG - 1; ++t) { load_stage(t); CP_COMMIT(); }

    for (int t = 0; t < NC; ++t) {
        CP_WAIT2();
        __syncthreads();
        if (t + NSTG - 1 < NC) load_stage(t + NSTG - 1);
        CP_COMMIT();

        const float* fA = (const float*)(smem + (t & (NSTG - 1)) * STAGEB);
        const float* fB = (const float*)(smem + (t & (NSTG - 1)) * STAGEB + TILEB);

        #pragma unroll
        for (int ks = 0; ks < 4; ++ks) {
            const int k0 = ks * 8;
            uint32_t a[2][4], b[8][2];
            #pragma unroll
            for (int mt = 0; mt < 2; ++mt) {
                const int row = wm * 32 + mt * 16 + g;
                a[mt][0] = __float_as_uint(fA[row * PADW + k0 + t4]);
                a[mt][1] = __float_as_uint(fA[(row + 8) * PADW + k0 + t4]);
                a[mt][2] = __float_as_uint(fA[row * PADW + k0 + t4 + 4]);
                a[mt][3] = __float_as_uint(fA[(row + 8) * PADW + k0 + t4 + 4]);
            }
            #pragma unroll
            for (int nt = 0; nt < 8; ++nt) {
                const int col = wn * 64 + nt * 8 + g;
                b[nt][0] = __float_as_uint(fB[col * PADW + k0 + t4]);
                b[nt][1] = __float_as_uint(fB[col * PADW + k0 + t4 + 4]);
            }
            #pragma unroll
            for (int mt = 0; mt < 2; ++mt)
                #pragma unroll
                for (int nt = 0; nt < 8; ++nt)
                    mma_tf32(acc[mt][nt][0], acc[mt][nt][1], acc[mt][nt][2], acc[mt][nt][3],
                             a[mt][0], a[mt][1], a[mt][2], a[mt][3],
                             b[nt][0], b[nt][1]);
        }
    }
    CP_WAIT0();
    __syncthreads();

    // ---------------- epilogue: stage via smem, coalesced float4 out ----------------
    float* stg = (float*)smem;   // 128 x 132
    #pragma unroll
    for (int mt = 0; mt < 2; ++mt) {
        #pragma unroll
        for (int nt = 0; nt < 8; ++nt) {
            const int row = wm * 32 + mt * 16 + g;
            const int col = wn * 64 + nt * 8 + t4 * 2;
            stg[row * 132 + col]       = acc[mt][nt][0];
            stg[row * 132 + col + 1]   = acc[mt][nt][1];
            stg[(row + 8) * 132 + col]     = acc[mt][nt][2];
            stg[(row + 8) * 132 + col + 1] = acc[mt][nt][3];
        }
    }
    __syncthreads();

    const int rr = tid >> 1;              // 0..127
    const int cb = (tid & 1) * 64;        // half selector
    float* yp = Y + (size_t)(m0 + rr) * O + n0 + cb;
    const float* bp = bias + n0 + cb;
    #pragma unroll
    for (int i = 0; i < 16; ++i) {
        float v0 = stg[rr * 132 + cb + i * 4 + 0] + bp[i * 4 + 0];
        float v1 = stg[rr * 132 + cb + i * 4 + 1] + bp[i * 4 + 1];
        float v2 = stg[rr * 132 + cb + i * 4 + 2] + bp[i * 4 + 2];
        float v3 = stg[rr * 132 + cb + i * 4 + 3] + bp[i * 4 + 3];
        if (RELU) {
            v0 = fmaxf(v0, 0.f); v1 = fmaxf(v1, 0.f);
            v2 = fmaxf(v2, 0.f); v3 = fmaxf(v3, 0.f);
        }
        float4 o = {v0, v1, v2, v3};
        *(float4*)(yp + i * 4) = o;
    }
}

// ---------------- attention S (split over n-chunks) ----------------
__global__ __launch_bounds__(256) void attn_s_kernel()
{
    int bh = blockIdx.x, ch = blockIdx.y;
    int b = bh >> 2, h = bh & 3;
    __shared__ float Qs[32][68];
    __shared__ float Ks[32][68];
    int tid = threadIdx.x;
    int tx = tid & 15, ty = tid >> 4;
    float acc[4][4] = {};
    const float* base = g_qkv + (size_t)b * kN * kC3 + h * kHD;
    int n0 = ch * 256;
    for (int nt = 0; nt < 8; ++nt) {
        int n1 = n0 + nt * 32;
        #pragma unroll
        for (int r = 0; r < 2; ++r) {
            int idx = r * 256 + tid;
            int nn = idx >> 4;
            int e4 = (idx & 15) << 2;
            const float* p = base + (size_t)(n1 + nn) * kC3 + e4;
            float4 q  = *(const float4*)p;
            float4 kv = *(const float4*)(p + kC);
            Qs[nn][e4 + 0] = q.x * 0.125f; Qs[nn][e4 + 1] = q.y * 0.125f;
            Qs[nn][e4 + 2] = q.z * 0.125f; Qs[nn][e4 + 3] = q.w * 0.125f;
            Ks[nn][e4 + 0] = kv.x; Ks[nn][e4 + 1] = kv.y;
            Ks[nn][e4 + 2] = kv.z; Ks[nn][e4 + 3] = kv.w;
        }
        __syncthreads();
        #pragma unroll 8
        for (int nn = 0; nn < 32; ++nn) {
            float qf[4], kf[4];
            *(float4*)qf = *(const float4*)&Qs[nn][ty * 4];
            *(float4*)kf = *(const float4*)&Ks[nn][tx * 4];
            #pragma unroll
            for (int i = 0; i < 4; ++i)
                #pragma unroll
                for (int j = 0; j < 4; ++j)
                    acc[i][j] += qf[i] * kf[j];
        }
        __syncthreads();
    }
    float* sp = g_spart + (size_t)(bh * kNCH + ch) * kHD * kHD;
    #pragma unroll
    for (int i = 0; i < 4; ++i)
        #pragma unroll
        for (int j = 0; j < 4; ++j)
            sp[(ty * 4 + i) * kHD + tx * 4 + j] = acc[i][j];
}

// ---------------- softmax (reduce partials, store transposed) ----------------
__global__ __launch_bounds__(256) void softmax_kernel()
{
    int bh = blockIdx.x;
    int dd = blockIdx.y * 8 + (threadIdx.x >> 5);
    int lane = threadIdx.x & 31;
    const float* spb = g_spart + (size_t)bh * kNCH * kHD * kHD + dd * kHD;
    float v0 = 0.f, v1 = 0.f;
    #pragma unroll
    for (int p = 0; p < kNCH; ++p) {
        v0 += spb[(size_t)p * kHD * kHD + lane];
        v1 += spb[(size_t)p * kHD * kHD + 32 + lane];
    }
    float m = fmaxf(v0, v1);
    #pragma unroll
    for (int off = 16; off; off >>= 1) m = fmaxf(m, __shfl_xor_sync(0xffffffffu, m, off));
    v0 = expf(v0 - m); v1 = expf(v1 - m);
    float s = v0 + v1;
    #pragma unroll
    for (int off = 16; off; off >>= 1) s += __shfl_xor_sync(0xffffffffu, s, off);
    float inv = 1.f / s;
    float* at = g_attn + (size_t)bh * kHD * kHD;
    at[lane * kHD + dd]        = v0 * inv;
    at[(32 + lane) * kHD + dd] = v1 * inv;
}

// ---------------- attn @ V -> (B,N,C) ----------------
__global__ __launch_bounds__(256) void attn_av_kernel()
{
    int bh = blockIdx.y;
    int b = bh >> 2, h = bh & 3;
    int n0 = blockIdx.x * 64;
    __shared__ float Vs[64][68];
    __shared__ float At[64][68];
    int tid = threadIdx.x;
    const float* vbase = g_qkv + (size_t)b * kN * kC3 + 2 * kC + h * kHD;
    const float* abase = g_attn + (size_t)bh * kHD * kHD;
    #pragma unroll
    for (int r = 0; r < 4; ++r) {
        int idx = r * 256 + tid;
        int nn = idx >> 4;
        int e4 = (idx & 15) << 2;
        *(float4*)&Vs[nn][e4] = *(const float4*)(vbase + (size_t)(n0 + nn) * kC3 + e4);
        *(float4*)&At[nn][e4] = *(const float4*)(abase + nn * kHD + e4);
    }
    __syncthreads();
    int tx = tid & 15, ty = tid >> 4;
    float acc[4][4] = {};
    #pragma unroll 4
    for (int e = 0; e < 64; ++e) {
        float va[4], at[4];
        va[0] = Vs[ty * 4 + 0][e];
        va[1] = Vs[ty * 4 + 1][e];
        va[2] = Vs[ty * 4 + 2][e];
        va[3] = Vs[ty * 4 + 3][e];
        *(float4*)at = *(const float4*)&At[e][tx * 4];
        #pragma unroll
        for (int i = 0; i < 4; ++i)
            #pragma unroll
            for (int j = 0; j < 4; ++j)
                acc[i][j] += va[i] * at[j];
    }
    float* yb = g_attnout + ((size_t)b * kN + n0) * kC + h * kHD + tx * 4;
    #pragma unroll
    for (int i = 0; i < 4; ++i) {
        float4 o = {acc[i][0], acc[i][1], acc[i][2], acc[i][3]};
        *(float4*)(yb + (size_t)(ty * 4 + i) * kC) = o;
    }
}

// ---------------- LN2 over rows of g_proj ----------------
__global__ __launch_bounds__(256) void ln2_kernel(const float* __restrict__ g2,
                                                  const float* __restrict__ be2)
{
    int row  = blockIdx.x * 8 + (threadIdx.x >> 5);
    int lane = threadIdx.x & 31;
    const float* p = g_proj + (size_t)row * kC;
    float4 a = *(const float4*)(p + lane * 4);
    float4 c = *(const float4*)(p + 128 + lane * 4);
    float s = a.x + a.y + a.z + a.w + c.x + c.y + c.z + c.w;
    float q = a.x * a.x + a.y * a.y + a.z * a.z + a.w * a.w
            + c.x * c.x + c.y * c.y + c.z * c.z + c.w * c.w;
    #pragma unroll
    for (int off = 16; off; off >>= 1) {
        s += __shfl_xor_sync(0xffffffffu, s, off);
        q += __shfl_xor_sync(0xffffffffu, q, off);
    }
    float mu = s * (1.f / 256.f);
    float rs = rsqrtf(q * (1.f / 256.f) - mu * mu + 1e-5f);
    int c0 = lane * 4, c1 = 128 + lane * 4;
    float* o = g_ln2 + (size_t)row * kC;
    float4 o0, o1;
    o0.x = (a.x - mu) * rs * g2[c0 + 0] + be2[c0 + 0];
    o0.y = (a.y - mu) * rs * g2[c0 + 1] + be2[c0 + 1];
    o0.z = (a.z - mu) * rs * g2[c0 + 2] + be2[c0 + 2];
    o0.w = (a.w - mu) * rs * g2[c0 + 3] + be2[c0 + 3];
    o1.x = (c.x - mu) * rs * g2[c1 + 0] + be2[c1 + 0];
    o1.y = (c.y - mu) * rs * g2[c1 + 1] + be2[c1 + 1];
    o1.z = (c.z - mu) * rs * g2[c1 + 2] + be2[c1 + 2];
    o1.w = (c.w - mu) * rs * g2[c1 + 3] + be2[c1 + 3];
    *(float4*)(o + c0) = o0;
    *(float4*)(o + c1) = o1;
}

// ---------------- transpose (B,N,C)->(B,C,N) + residual ----------------
__global__ __launch_bounds__(256) void resid_kernel(const float* __restrict__ x,
                                                    float* __restrict__ out)
{
    int b = blockIdx.z, c0 = blockIdx.y * 32, n0 = blockIdx.x * 32;
    __shared__ float s[32][33];
    int tid = threadIdx.x;
    const float* fb = g_ffo + ((size_t)b * kN + n0) * kC + c0;
    #pragma unroll
    for (int r = 0; r < 4; ++r) {
        int idx = r * 256 + tid;
        int nn = idx >> 5, cc = idx & 31;
        s[nn][cc] = fb[(size_t)nn * kC + cc];
    }
    __syncthreads();
    const float* xb = x + ((size_t)b * kC + c0) * kN + n0;
    float* ob = out + ((size_t)b * kC + c0) * kN + n0;
    #pragma unroll
    for (int r = 0; r < 4; ++r) {
        int idx = r * 256 + tid;
        int cc = idx >> 5, nn = idx & 31;
        ob[(size_t)cc * kN + nn] = s[nn][cc] + xb[(size_t)cc * kN + nn];
    }
}

// ---------------- launch ----------------
extern "C" void kernel_launch(void* const* d_in, const int* in_sizes, int n_in,
                              void* d_out, int out_size)
{
    const float* x      = (const float*)d_in[0];
    const float* w_qkv  = (const float*)d_in[1];
    const float* b_qkv  = (const float*)d_in[2];
    const float* w_proj = (const float*)d_in[3];
    const float* b_proj = (const float*)d_in[4];
    const float* w_ffn1 = (const float*)d_in[5];
    const float* b_ffn1 = (const float*)d_in[6];
    const float* w_ffn2 = (const float*)d_in[7];
    const float* b_ffn2 = (const float*)d_in[8];
    const float* g1     = (const float*)d_in[9];
    const float* be1    = (const float*)d_in[10];
    const float* g2     = (const float*)d_in[11];
    const float* be2    = (const float*)d_in[12];
    float* out = (float*)d_out;

    void *p_xln, *p_qkv, *p_attnout, *p_proj, *p_ln2, *p_ffh, *p_ffo;
    cudaGetSymbolAddress(&p_xln, g_xln);
    cudaGetSymbolAddress(&p_qkv, g_qkv);
    cudaGetSymbolAddress(&p_attnout, g_attnout);
    cudaGetSymbolAddress(&p_proj, g_proj);
    cudaGetSymbolAddress(&p_ln2, g_ln2);
    cudaGetSymbolAddress(&p_ffh, g_ffh);
    cudaGetSymbolAddress(&p_ffo, g_ffo);

    cudaFuncSetAttribute(gemm_mma<false>, cudaFuncAttributeMaxDynamicSharedMemorySize, SMEM_DYN);
    cudaFuncSetAttribute(gemm_mma<true>,  cudaFuncAttributeMaxDynamicSharedMemorySize, SMEM_DYN);

    const int M = kB * kN;  // 32768

    ln1_kernel<<<dim3(kN / 32, kB), 256>>>(x, g1, be1);

    // QKV: (M x 256) @ (768 x 256)^T
    gemm_mma<false><<<dim3(kC3 / 128, M / 128), 256, SMEM_DYN>>>(
        (const float*)p_xln, w_qkv, b_qkv, (float*)p_qkv, kC, kC3);

    attn_s_kernel<<<dim3(kBH, kNCH), 256>>>();
    softmax_kernel<<<dim3(kBH, 8), 256>>>();
    attn_av_kernel<<<dim3(kN / 64, kBH), 256>>>();

    // proj: (M x 256) @ (256 x 256)^T
    gemm_mma<false><<<dim3(kC / 128, M / 128), 256, SMEM_DYN>>>(
        (const float*)p_attnout, w_proj, b_proj, (float*)p_proj, kC, kC);

    ln2_kernel<<<M / 8, 256>>>(g2, be2);

    // FFN1 + ReLU: (M x 256) @ (2048 x 256)^T
    gemm_mma<true><<<dim3(kFFN / 128, M / 128), 256, SMEM_DYN>>>(
        (const float*)p_ln2, w_ffn1, b_ffn1, (float*)p_ffh, kC, kFFN);

    // FFN2: (M x 2048) @ (256 x 2048)^T
    gemm_mma<false><<<dim3(kC / 128, M / 128), 256, SMEM_DYN>>>(
        (const float*)p_ffh, w_ffn2, b_ffn2, (float*)p_ffo, kFFN, kC);

    resid_kernel<<<dim3(kN / 32, kC / 32, kB), 256>>>(x, out);
}

// round 4
// speedup vs baseline: 3.9365x; 1.7572x over previous
#include <cuda_runtime.h>
#include <cuda_fp16.h>
#include <cstdint>

// ---------------- problem constants ----------------
namespace {
constexpr int kB   = 8;
constexpr int kC   = 256;
constexpr int kN   = 4096;
constexpr int kC3  = 768;
constexpr int kFFN = 2048;
constexpr int kHD  = 64;
constexpr int kBH  = 32;
constexpr int kNCH = 16;

constexpr int ROWH   = 40;                  // padded row length in halves (80B, 16B-aligned)
constexpr int ROWW   = 20;                  // in 32-bit words
constexpr int TILEB  = 128 * ROWH * 2;      // 10240 bytes per operand tile (K-chunk 32)
constexpr int STAGEB = 2 * TILEB;           // 20480
constexpr int NSTG   = 4;
constexpr uint32_t SMEM_DYN = STAGEB * NSTG; // 81920 (epilogue needs 128*133*4=68096, fits)

// packed fp16 weights offsets
constexpr int OW_QKV  = 0;
constexpr int OW_PROJ = OW_QKV + kC3 * kC;           // 196608
constexpr int OW_FFN1 = OW_PROJ + kC * kC;           // 262144
constexpr int OW_FFN2 = OW_FFN1 + kFFN * kC;         // 786432
constexpr int OW_TOT  = OW_FFN2 + kC * kFFN;         // 1310720
}

// ---------------- scratch ----------------
__device__ __half h_xln[kB * kN * kC];
__device__ __half h_qkv[kB * kN * kC3];
__device__ float  g_spart[kBH * kNCH * kHD * kHD];
__device__ float  g_attn[kBH * kHD * kHD];
__device__ __half h_attnout[kB * kN * kC];
__device__ __half h_proj[kB * kN * kC];
__device__ __half h_ln2[kB * kN * kC];
__device__ __half h_ffh[kB * kN * kFFN];
__device__ __half h_w[OW_TOT];

// ---------------- helpers ----------------
__device__ __forceinline__ uint32_t smem_u32(const void* p) {
    uint32_t a;
    asm("{ .reg .u64 t; cvta.to.shared.u64 t, %1; cvt.u32.u64 %0, t; }" : "=r"(a) : "l"(p));
    return a;
}
__device__ __forceinline__ void cp_async16(uint32_t s, const void* g) {
    asm volatile("cp.async.cg.shared.global [%0], [%1], 16;" :: "r"(s), "l"(g));
}
#define CP_COMMIT() asm volatile("cp.async.commit_group;" ::: "memory")
#define CP_WAIT2()  asm volatile("cp.async.wait_group 2;" ::: "memory")
#define CP_WAIT0()  asm volatile("cp.async.wait_group 0;" ::: "memory")

__device__ __forceinline__ void mma_f16(float& c0, float& c1, float& c2, float& c3,
                                        uint32_t a0, uint32_t a1, uint32_t a2, uint32_t a3,
                                        uint32_t b0, uint32_t b1) {
    asm volatile(
        "mma.sync.aligned.m16n8k16.row.col.f32.f16.f16.f32 "
        "{%0,%1,%2,%3}, {%4,%5,%6,%7}, {%8,%9}, {%0,%1,%2,%3};"
        : "+f"(c0), "+f"(c1), "+f"(c2), "+f"(c3)
        : "r"(a0), "r"(a1), "r"(a2), "r"(a3), "r"(b0), "r"(b1));
}

// ---------------- weight conversion fp32 -> fp16 (packed) ----------------
__global__ __launch_bounds__(256) void convw_kernel(const float* __restrict__ wqkv,
                                                    const float* __restrict__ wproj,
                                                    const float* __restrict__ wffn1,
                                                    const float* __restrict__ wffn2)
{
    int i = blockIdx.x * 256 + threadIdx.x;
    if (i >= OW_TOT) return;
    float v;
    if (i < OW_PROJ)       v = wqkv[i - OW_QKV];
    else if (i < OW_FFN1)  v = wproj[i - OW_PROJ];
    else if (i < OW_FFN2)  v = wffn1[i - OW_FFN1];
    else                   v = wffn2[i - OW_FFN2];
    h_w[i] = __float2half(v);
}

// ---------------- LN1: (B,C,N) fp32 -> LN over C -> (B,N,C) fp16 ----------------
__global__ __launch_bounds__(256) void ln1_kernel(const float* __restrict__ x,
                                                  const float* __restrict__ g1,
                                                  const float* __restrict__ be1)
{
    __shared__ float s[32][257];
    __shared__ float smu[32], srs[32];
    int b  = blockIdx.y;
    int n0 = blockIdx.x * 32;
    int tid = threadIdx.x;
    const float* xb = x + (size_t)b * kC * kN;
    #pragma unroll
    for (int it = 0; it < 32; ++it) {
        int idx = it * 256 + tid;
        int c = idx >> 5, nn = idx & 31;
        s[nn][c] = xb[(size_t)c * kN + n0 + nn];
    }
    __syncthreads();
    int nn = tid >> 3, g = tid & 7;
    float sum = 0.f, sq = 0.f;
    #pragma unroll
    for (int j = 0; j < 32; ++j) { float v = s[nn][g + j * 8]; sum += v; sq += v * v; }
    sum += __shfl_xor_sync(0xffffffffu, sum, 1, 8);
    sum += __shfl_xor_sync(0xffffffffu, sum, 2, 8);
    sum += __shfl_xor_sync(0xffffffffu, sum, 4, 8);
    sq  += __shfl_xor_sync(0xffffffffu, sq, 1, 8);
    sq  += __shfl_xor_sync(0xffffffffu, sq, 2, 8);
    sq  += __shfl_xor_sync(0xffffffffu, sq, 4, 8);
    if (g == 0) {
        float mu = sum * (1.f / 256.f);
        smu[nn] = mu;
        srs[nn] = rsqrtf(sq * (1.f / 256.f) - mu * mu + 1e-5f);
    }
    __syncthreads();
    float gg = g1[tid], bb = be1[tid];
    __half* yb = h_xln + ((size_t)b * kN + n0) * kC;
    #pragma unroll
    for (int it = 0; it < 32; ++it)
        yb[(size_t)it * kC + tid] = __float2half((s[it][tid] - smu[it]) * srs[it] * gg + bb);
}

// ---------------- fp16 tensor-core GEMM, tile 128x128x32 ----------------
// A: MxK fp16 row-major; W: OxK fp16 row-major; acc fp32.
// MODE 0: Y = fp16, plain + bias. MODE 1: Y = fp16, bias + ReLU.
// MODE 2: Y = fp32 out tensor (B,C,N), fused bias + residual + transpose.
template <int MODE>
__global__ __launch_bounds__(256) void gemm_h(const __half* __restrict__ A,
                                              const __half* __restrict__ W,
                                              const float* __restrict__ bias,
                                              void* __restrict__ Yv,
                                              const float* __restrict__ xres,
                                              int K, int O)
{
    extern __shared__ __align__(16) char smem[];
    const uint32_t sbase = smem_u32(smem);
    const int tid = threadIdx.x;
    const int lane = tid & 31;
    const int wid = tid >> 5;
    const int g  = lane >> 2;
    const int t4 = lane & 3;
    const int wm = wid >> 1;       // 0..3
    const int wn = wid & 1;        // 0..1
    const int m0 = blockIdx.y * 128;
    const int n0 = blockIdx.x * 128;
    const int NC = K >> 5;

    const int r_ld = tid >> 2;     // 0..63
    const int c_ld = tid & 3;      // 16B chunk (8 halves)

    float acc[2][8][4];
    #pragma unroll
    for (int i = 0; i < 2; ++i)
        #pragma unroll
        for (int j = 0; j < 8; ++j)
            #pragma unroll
            for (int r = 0; r < 4; ++r) acc[i][j][r] = 0.f;

    auto load_stage = [&](int t) {
        const uint32_t sA = sbase + (t & (NSTG - 1)) * STAGEB;
        const uint32_t sB = sA + TILEB;
        const int k0 = t * 32;
        const __half* Ag = A + (size_t)(m0 + r_ld) * K + k0 + c_ld * 8;
        const __half* Wg = W + (size_t)(n0 + r_ld) * K + k0 + c_ld * 8;
        #pragma unroll
        for (int p = 0; p < 2; ++p) {
            cp_async16(sA + (p * 64 + r_ld) * (ROWH * 2) + c_ld * 16, Ag + (size_t)(p * 64) * K);
            cp_async16(sB + (p * 64 + r_ld) * (ROWH * 2) + c_ld * 16, Wg + (size_t)(p * 64) * K);
        }
    };

    #pragma unroll
    for (int t = 0; t < NSTG - 1; ++t) { load_stage(t); CP_COMMIT(); }

    for (int t = 0; t < NC; ++t) {
        CP_WAIT2();
        __syncthreads();
        if (t + NSTG - 1 < NC) load_stage(t + NSTG - 1);
        CP_COMMIT();

        const uint32_t* fA = (const uint32_t*)(smem + (t & (NSTG - 1)) * STAGEB);
        const uint32_t* fB = (const uint32_t*)(smem + (t & (NSTG - 1)) * STAGEB + TILEB);

        #pragma unroll
        for (int ks = 0; ks < 2; ++ks) {
            const int kw = ks * 8;     // word offset within row
            uint32_t a[2][4], b[8][2];
            #pragma unroll
            for (int mt = 0; mt < 2; ++mt) {
                const int row = wm * 32 + mt * 16 + g;
                a[mt][0] = fA[row * ROWW + kw + t4];
                a[mt][1] = fA[(row + 8) * ROWW + kw + t4];
                a[mt][2] = fA[row * ROWW + kw + t4 + 4];
                a[mt][3] = fA[(row + 8) * ROWW + kw + t4 + 4];
            }
            #pragma unroll
            for (int nt = 0; nt < 8; ++nt) {
                const int col = wn * 64 + nt * 8 + g;
                b[nt][0] = fB[col * ROWW + kw + t4];
                b[nt][1] = fB[col * ROWW + kw + t4 + 4];
            }
            #pragma unroll
            for (int mt = 0; mt < 2; ++mt)
                #pragma unroll
                for (int nt = 0; nt < 8; ++nt)
                    mma_f16(acc[mt][nt][0], acc[mt][nt][1], acc[mt][nt][2], acc[mt][nt][3],
                            a[mt][0], a[mt][1], a[mt][2], a[mt][3],
                            b[nt][0], b[nt][1]);
        }
    }
    CP_WAIT0();
    __syncthreads();

    // ---------------- epilogue: stage fp32 in smem (stride 133) ----------------
    float* stg = (float*)smem;
    #pragma unroll
    for (int mt = 0; mt < 2; ++mt) {
        #pragma unroll
        for (int nt = 0; nt < 8; ++nt) {
            const int row = wm * 32 + mt * 16 + g;
            const int col = wn * 64 + nt * 8 + t4 * 2;
            stg[row * 133 + col]           = acc[mt][nt][0];
            stg[row * 133 + col + 1]       = acc[mt][nt][1];
            stg[(row + 8) * 133 + col]     = acc[mt][nt][2];
            stg[(row + 8) * 133 + col + 1] = acc[mt][nt][3];
        }
    }
    __syncthreads();

    if (MODE != 2) {
        __half* Y = (__half*)Yv;
        const int rr = tid >> 1;
        const int cb = (tid & 1) * 64;
        __half* yp = Y + (size_t)(m0 + rr) * O + n0 + cb;
        const float* bp = bias + n0 + cb;
        #pragma unroll
        for (int i = 0; i < 8; ++i) {
            __half2 h[4];
            #pragma unroll
            for (int q = 0; q < 4; ++q) {
                float v0 = stg[rr * 133 + cb + i * 8 + q * 2]     + bp[i * 8 + q * 2];
                float v1 = stg[rr * 133 + cb + i * 8 + q * 2 + 1] + bp[i * 8 + q * 2 + 1];
                if (MODE == 1) { v0 = fmaxf(v0, 0.f); v1 = fmaxf(v1, 0.f); }
                h[q] = __floats2half2_rn(v0, v1);
            }
            *(uint4*)(yp + i * 8) = *(uint4*)h;
        }
    } else {
        // fused bias + residual + transpose to (B,C,N)
        float* Y = (float*)Yv;
        const int bidx = m0 >> 12;          // batch (128 | 4096)
        const int npix = m0 & 4095;
        #pragma unroll
        for (int ci = 0; ci < 16; ++ci) {
            const int c = wid * 16 + ci;
            const int cg = n0 + c;
            const float bv = bias[cg];
            const size_t base = (((size_t)(bidx * 256 + cg)) << 12) + npix;
            #pragma unroll
            for (int i = 0; i < 4; ++i) {
                const int m = lane + 32 * i;
                Y[base + m] = stg[m * 133 + c] + bv + xres[base + m];
            }
        }
    }
}

// ---------------- attention S (split over n-chunks), fp16 in / fp32 acc ----------------
__global__ __launch_bounds__(256) void attn_s_kernel()
{
    int bh = blockIdx.x, ch = blockIdx.y;
    int b = bh >> 2, h = bh & 3;
    __shared__ float Qs[32][68];
    __shared__ float Ks[32][68];
    int tid = threadIdx.x;
    int tx = tid & 15, ty = tid >> 4;
    float acc[4][4] = {};
    const __half* base = h_qkv + (size_t)b * kN * kC3 + h * kHD;
    int n0 = ch * 256;
    for (int nt = 0; nt < 8; ++nt) {
        int n1 = n0 + nt * 32;
        #pragma unroll
        for (int r = 0; r < 2; ++r) {
            int idx = r * 256 + tid;
            int nn = idx >> 4;
            int e4 = (idx & 15) << 2;
            const __half2* p = (const __half2*)(base + (size_t)(n1 + nn) * kC3 + e4);
            __half2 q0 = p[0], q1 = p[1];
            __half2 k0 = p[128], k1 = p[129];   // k part lives +256 halves
            float2 qa = __half22float2(q0), qb = __half22float2(q1);
            float2 ka = __half22float2(k0), kb = __half22float2(k1);
            Qs[nn][e4 + 0] = qa.x * 0.125f; Qs[nn][e4 + 1] = qa.y * 0.125f;
            Qs[nn][e4 + 2] = qb.x * 0.125f; Qs[nn][e4 + 3] = qb.y * 0.125f;
            Ks[nn][e4 + 0] = ka.x; Ks[nn][e4 + 1] = ka.y;
            Ks[nn][e4 + 2] = kb.x; Ks[nn][e4 + 3] = kb.y;
        }
        __syncthreads();
        #pragma unroll 8
        for (int nn = 0; nn < 32; ++nn) {
            float qf[4], kf[4];
            *(float4*)qf = *(const float4*)&Qs[nn][ty * 4];
            *(float4*)kf = *(const float4*)&Ks[nn][tx * 4];
            #pragma unroll
            for (int i = 0; i < 4; ++i)
                #pragma unroll
                for (int j = 0; j < 4; ++j)
                    acc[i][j] += qf[i] * kf[j];
        }
        __syncthreads();
    }
    float* sp = g_spart + (size_t)(bh * kNCH + ch) * kHD * kHD;
    #pragma unroll
    for (int i = 0; i < 4; ++i)
        #pragma unroll
        for (int j = 0; j < 4; ++j)
            sp[(ty * 4 + i) * kHD + tx * 4 + j] = acc[i][j];
}

// ---------------- softmax (reduce partials, store transposed) ----------------
__global__ __launch_bounds__(256) void softmax_kernel()
{
    int bh = blockIdx.x;
    int dd = blockIdx.y * 8 + (threadIdx.x >> 5);
    int lane = threadIdx.x & 31;
    const float* spb = g_spart + (size_t)bh * kNCH * kHD * kHD + dd * kHD;
    float v0 = 0.f, v1 = 0.f;
    #pragma unroll
    for (int p = 0; p < kNCH; ++p) {
        v0 += spb[(size_t)p * kHD * kHD + lane];
        v1 += spb[(size_t)p * kHD * kHD + 32 + lane];
    }
    float m = fmaxf(v0, v1);
    #pragma unroll
    for (int off = 16; off; off >>= 1) m = fmaxf(m, __shfl_xor_sync(0xffffffffu, m, off));
    v0 = expf(v0 - m); v1 = expf(v1 - m);
    float s = v0 + v1;
    #pragma unroll
    for (int off = 16; off; off >>= 1) s += __shfl_xor_sync(0xffffffffu, s, off);
    float inv = 1.f / s;
    float* at = g_attn + (size_t)bh * kHD * kHD;
    at[lane * kHD + dd]        = v0 * inv;
    at[(32 + lane) * kHD + dd] = v1 * inv;
}

// ---------------- attn @ V -> (B,N,C) fp16 ----------------
__global__ __launch_bounds__(256) void attn_av_kernel()
{
    int bh = blockIdx.y;
    int b = bh >> 2, h = bh & 3;
    int n0 = blockIdx.x * 64;
    __shared__ float Vs[64][68];
    __shared__ float At[64][68];
    int tid = threadIdx.x;
    const __half* vbase = h_qkv + (size_t)b * kN * kC3 + 2 * kC + h * kHD;
    const float* abase = g_attn + (size_t)bh * kHD * kHD;
    #pragma unroll
    for (int r = 0; r < 4; ++r) {
        int idx = r * 256 + tid;
        int nn = idx >> 4;
        int e4 = (idx & 15) << 2;
        const __half2* vp = (const __half2*)(vbase + (size_t)(n0 + nn) * kC3 + e4);
        __half2 v0 = vp[0], v1 = vp[1];
        float2 va = __half22float2(v0), vb = __half22float2(v1);
        Vs[nn][e4 + 0] = va.x; Vs[nn][e4 + 1] = va.y;
        Vs[nn][e4 + 2] = vb.x; Vs[nn][e4 + 3] = vb.y;
        *(float4*)&At[nn][e4] = *(const float4*)(abase + nn * kHD + e4);
    }
    __syncthreads();
    int tx = tid & 15, ty = tid >> 4;
    float acc[4][4] = {};
    #pragma unroll 4
    for (int e = 0; e < 64; ++e) {
        float va[4], at[4];
        va[0] = Vs[ty * 4 + 0][e];
        va[1] = Vs[ty * 4 + 1][e];
        va[2] = Vs[ty * 4 + 2][e];
        va[3] = Vs[ty * 4 + 3][e];
        *(float4*)at = *(const float4*)&At[e][tx * 4];
        #pragma unroll
        for (int i = 0; i < 4; ++i)
            #pragma unroll
            for (int j = 0; j < 4; ++j)
                acc[i][j] += va[i] * at[j];
    }
    __half* yb = h_attnout + ((size_t)b * kN + n0) * kC + h * kHD + tx * 4;
    #pragma unroll
    for (int i = 0; i < 4; ++i) {
        __half2 o0 = __floats2half2_rn(acc[i][0], acc[i][1]);
        __half2 o1 = __floats2half2_rn(acc[i][2], acc[i][3]);
        __half2* op = (__half2*)(yb + (size_t)(ty * 4 + i) * kC);
        op[0] = o0; op[1] = o1;
    }
}

// ---------------- LN2: h_proj (fp16) -> h_ln2 (fp16) ----------------
__global__ __launch_bounds__(256) void ln2_kernel(const float* __restrict__ g2,
                                                  const float* __restrict__ be2)
{
    int row  = blockIdx.x * 8 + (threadIdx.x >> 5);
    int lane = threadIdx.x & 31;
    const __half* p = h_proj + (size_t)row * kC + lane * 8;
    __half2 h[4];
    *(uint4*)h = *(const uint4*)p;
    float v[8];
    #pragma unroll
    for (int q = 0; q < 4; ++q) {
        float2 f = __half22float2(h[q]);
        v[q * 2] = f.x; v[q * 2 + 1] = f.y;
    }
    float s = 0.f, qq = 0.f;
    #pragma unroll
    for (int j = 0; j < 8; ++j) { s += v[j]; qq += v[j] * v[j]; }
    #pragma unroll
    for (int off = 16; off; off >>= 1) {
        s  += __shfl_xor_sync(0xffffffffu, s, off);
        qq += __shfl_xor_sync(0xffffffffu, qq, off);
    }
    float mu = s * (1.f / 256.f);
    float rs = rsqrtf(qq * (1.f / 256.f) - mu * mu + 1e-5f);
    const int c0 = lane * 8;
    __half2 o[4];
    #pragma unroll
    for (int q = 0; q < 4; ++q) {
        float o0 = (v[q * 2]     - mu) * rs * g2[c0 + q * 2]     + be2[c0 + q * 2];
        float o1 = (v[q * 2 + 1] - mu) * rs * g2[c0 + q * 2 + 1] + be2[c0 + q * 2 + 1];
        o[q] = __floats2half2_rn(o0, o1);
    }
    *(uint4*)(h_ln2 + (size_t)row * kC + c0) = *(uint4*)o;
}

// ---------------- launch ----------------
extern "C" void kernel_launch(void* const* d_in, const int* in_sizes, int n_in,
                              void* d_out, int out_size)
{
    const float* x      = (const float*)d_in[0];
    const float* w_qkv  = (const float*)d_in[1];
    const float* b_qkv  = (const float*)d_in[2];
    const float* w_proj = (const float*)d_in[3];
    const float* b_proj = (const float*)d_in[4];
    const float* w_ffn1 = (const float*)d_in[5];
    const float* b_ffn1 = (const float*)d_in[6];
    const float* w_ffn2 = (const float*)d_in[7];
    const float* b_ffn2 = (const float*)d_in[8];
    const float* g1     = (const float*)d_in[9];
    const float* be1    = (const float*)d_in[10];
    const float* g2     = (const float*)d_in[11];
    const float* be2    = (const float*)d_in[12];
    float* out = (float*)d_out;

    void *p_xln, *p_qkv, *p_attnout, *p_proj, *p_ln2, *p_ffh, *p_w;
    cudaGetSymbolAddress(&p_xln, h_xln);
    cudaGetSymbolAddress(&p_qkv, h_qkv);
    cudaGetSymbolAddress(&p_attnout, h_attnout);
    cudaGetSymbolAddress(&p_proj, h_proj);
    cudaGetSymbolAddress(&p_ln2, h_ln2);
    cudaGetSymbolAddress(&p_ffh, h_ffh);
    cudaGetSymbolAddress(&p_w, h_w);
    const __half* hw = (const __half*)p_w;

    cudaFuncSetAttribute(gemm_h<0>, cudaFuncAttributeMaxDynamicSharedMemorySize, SMEM_DYN);
    cudaFuncSetAttribute(gemm_h<1>, cudaFuncAttributeMaxDynamicSharedMemorySize, SMEM_DYN);
    cudaFuncSetAttribute(gemm_h<2>, cudaFuncAttributeMaxDynamicSharedMemorySize, SMEM_DYN);

    const int M = kB * kN;  // 32768

    convw_kernel<<<(OW_TOT + 255) / 256, 256>>>(w_qkv, w_proj, w_ffn1, w_ffn2);

    ln1_kernel<<<dim3(kN / 32, kB), 256>>>(x, g1, be1);

    // QKV: (M x 256) @ (768 x 256)^T -> fp16
    gemm_h<0><<<dim3(kC3 / 128, M / 128), 256, SMEM_DYN>>>(
        (const __half*)p_xln, hw + OW_QKV, b_qkv, p_qkv, nullptr, kC, kC3);

    attn_s_kernel<<<dim3(kBH, kNCH), 256>>>();
    softmax_kernel<<<dim3(kBH, 8), 256>>>();
    attn_av_kernel<<<dim3(kN / 64, kBH), 256>>>();

    // proj: (M x 256) @ (256 x 256)^T -> fp16
    gemm_h<0><<<dim3(kC / 128, M / 128), 256, SMEM_DYN>>>(
        (const __half*)p_attnout, hw + OW_PROJ, b_proj, p_proj, nullptr, kC, kC);

    ln2_kernel<<<M / 8, 256>>>(g2, be2);

    // FFN1 + ReLU: (M x 256) @ (2048 x 256)^T -> fp16
    gemm_h<1><<<dim3(kFFN / 128, M / 128), 256, SMEM_DYN>>>(
        (const __half*)p_ln2, hw + OW_FFN1, b_ffn1, p_ffh, nullptr, kC, kFFN);

    // FFN2 + residual + transpose: (M x 2048) @ (256 x 2048)^T -> fp32 out (B,C,N)
    gemm_h<2><<<dim3(kC / 128, M / 128), 256, SMEM_DYN>>>(
        (const __half*)p_ffh, hw + OW_FFN2, b_ffn2, out, x, kFFN, kC);
}

// round 5
// speedup vs baseline: 4.6655x; 1.1852x over previous
#include <cuda_runtime.h>
#include <cuda_fp16.h>
#include <cstdint>

// ---------------- problem constants ----------------
namespace {
constexpr int kB   = 8;
constexpr int kC   = 256;
constexpr int kN   = 4096;
constexpr int kC3  = 768;
constexpr int kFFN = 2048;
constexpr int kBH  = 32;
constexpr int kNCH = 8;          // split-K chunks for attention S

constexpr int ROWH   = 40;                  // padded row length in halves (80B)
constexpr int TILEB  = 128 * ROWH * 2;      // 10240 bytes per operand tile (K-chunk 32)
constexpr int STAGEB = 2 * TILEB;           // 20480
constexpr int NSTG   = 4;
constexpr uint32_t SMEM_DYN = STAGEB * NSTG; // 81920

constexpr int OW_QKV  = 0;
constexpr int OW_PROJ = OW_QKV + kC3 * kC;
constexpr int OW_FFN1 = OW_PROJ + kC * kC;
constexpr int OW_FFN2 = OW_FFN1 + kFFN * kC;
constexpr int OW_TOT  = OW_FFN2 + kC * kFFN;
}

// ---------------- scratch ----------------
__device__ __half h_xln[kB * kN * kC];
__device__ __half h_qkT[4096 * 4096];        // [(qk*8+b)*4+h)*64+d][n]
__device__ __half h_v[kB * kN * kC];         // [(b,n)][h*64+e]
__device__ float  g_spart[kBH * kNCH * 64 * 64];
__device__ __half h_attnw[kBH * 64 * 64];    // softmaxed attn fp16, rows d, cols e
__device__ __half h_attnout[kB * kN * kC];
__device__ __half h_proj[kB * kN * kC];
__device__ __half h_ln2[kB * kN * kC];
__device__ __half h_ffh[kB * kN * kFFN];
__device__ __half h_w[OW_TOT];

// ---------------- helpers ----------------
__device__ __forceinline__ uint32_t smem_u32(const void* p) {
    uint32_t a;
    asm("{ .reg .u64 t; cvta.to.shared.u64 t, %1; cvt.u32.u64 %0, t; }" : "=r"(a) : "l"(p));
    return a;
}
__device__ __forceinline__ void cp_async16(uint32_t s, const void* g) {
    asm volatile("cp.async.cg.shared.global [%0], [%1], 16;" :: "r"(s), "l"(g));
}
#define CP_COMMIT() asm volatile("cp.async.commit_group;" ::: "memory")
#define CP_WAIT2()  asm volatile("cp.async.wait_group 2;" ::: "memory")
#define CP_WAIT0()  asm volatile("cp.async.wait_group 0;" ::: "memory")

__device__ __forceinline__ void ldsm4(uint32_t* r, uint32_t a) {
    asm volatile("ldmatrix.sync.aligned.m8n8.x4.shared.b16 {%0,%1,%2,%3}, [%4];"
                 : "=r"(r[0]), "=r"(r[1]), "=r"(r[2]), "=r"(r[3]) : "r"(a));
}

__device__ __forceinline__ void mma_f16(float* c,
                                        uint32_t a0, uint32_t a1, uint32_t a2, uint32_t a3,
                                        uint32_t b0, uint32_t b1) {
    asm volatile(
        "mma.sync.aligned.m16n8k16.row.col.f32.f16.f16.f32 "
        "{%0,%1,%2,%3}, {%4,%5,%6,%7}, {%8,%9}, {%0,%1,%2,%3};"
        : "+f"(c[0]), "+f"(c[1]), "+f"(c[2]), "+f"(c[3])
        : "r"(a0), "r"(a1), "r"(a2), "r"(a3), "r"(b0), "r"(b1));
}

// ---------------- weight conversion ----------------
__global__ __launch_bounds__(256) void convw_kernel(const float* __restrict__ wqkv,
                                                    const float* __restrict__ wproj,
                                                    const float* __restrict__ wffn1,
                                                    const float* __restrict__ wffn2)
{
    int i = blockIdx.x * 256 + threadIdx.x;
    if (i >= OW_TOT) return;
    float v;
    if (i < OW_PROJ)       v = wqkv[i - OW_QKV];
    else if (i < OW_FFN1)  v = wproj[i - OW_PROJ];
    else if (i < OW_FFN2)  v = wffn1[i - OW_FFN1];
    else                   v = wffn2[i - OW_FFN2];
    h_w[i] = __float2half(v);
}

// ---------------- LN1: (B,C,N) fp32 -> LN over C -> (B,N,C) fp16 ----------------
__global__ __launch_bounds__(256) void ln1_kernel(const float* __restrict__ x,
                                                  const float* __restrict__ g1,
                                                  const float* __restrict__ be1)
{
    __shared__ float s[32][257];
    __shared__ float smu[32], srs[32];
    int b  = blockIdx.y;
    int n0 = blockIdx.x * 32;
    int tid = threadIdx.x;
    const float* xb = x + (size_t)b * kC * kN;
    #pragma unroll
    for (int it = 0; it < 32; ++it) {
        int idx = it * 256 + tid;
        int c = idx >> 5, nn = idx & 31;
        s[nn][c] = xb[(size_t)c * kN + n0 + nn];
    }
    __syncthreads();
    int nn = tid >> 3, g = tid & 7;
    float sum = 0.f, sq = 0.f;
    #pragma unroll
    for (int j = 0; j < 32; ++j) { float v = s[nn][g + j * 8]; sum += v; sq += v * v; }
    sum += __shfl_xor_sync(0xffffffffu, sum, 1, 8);
    sum += __shfl_xor_sync(0xffffffffu, sum, 2, 8);
    sum += __shfl_xor_sync(0xffffffffu, sum, 4, 8);
    sq  += __shfl_xor_sync(0xffffffffu, sq, 1, 8);
    sq  += __shfl_xor_sync(0xffffffffu, sq, 2, 8);
    sq  += __shfl_xor_sync(0xffffffffu, sq, 4, 8);
    if (g == 0) {
        float mu = sum * (1.f / 256.f);
        smu[nn] = mu;
        srs[nn] = rsqrtf(sq * (1.f / 256.f) - mu * mu + 1e-5f);
    }
    __syncthreads();
    float gg = g1[tid], bb = be1[tid];
    __half* yb = h_xln + ((size_t)b * kN + n0) * kC;
    #pragma unroll
    for (int it = 0; it < 32; ++it)
        yb[(size_t)it * kC + tid] = __float2half((s[it][tid] - smu[it]) * srs[it] * gg + bb);
}

// ---------------- fp16 tensor GEMM 128x128x32, ldmatrix mainloop ----------------
// MODE 0: fp16 out + bias. MODE 1: fp16 out + bias + ReLU.
// MODE 2: fp32 out (B,C,N), fused bias + residual + transpose.
// MODE 3: QKV special — q,k tiles written transposed (q scaled 1/8) to h_qkT; v to h_v.
template <int MODE>
__global__ __launch_bounds__(256, 2) void gemm_h(const __half* __restrict__ A,
                                                 const __half* __restrict__ W,
                                                 const float* __restrict__ bias,
                                                 void* __restrict__ Yv,
                                                 const float* __restrict__ xres,
                                                 int K, int O)
{
    extern __shared__ __align__(16) char smem[];
    const uint32_t sbase = smem_u32(smem);
    const int tid = threadIdx.x;
    const int lane = tid & 31;
    const int wid = tid >> 5;
    const int g  = lane >> 2;
    const int t4 = lane & 3;
    const int wm = wid >> 1;
    const int wn = wid & 1;
    const int m0 = blockIdx.y * 128;
    const int n0 = blockIdx.x * 128;
    const int NC = K >> 5;

    const int r_ld = tid >> 2;
    const int c_ld = tid & 3;

    // ldmatrix lane offsets (conflict-free with 80B rows)
    const int quad = lane >> 3, lr = lane & 7;
    const uint32_t offA = (uint32_t)(wm * 32 + (quad & 1) * 8 + lr) * 80 + (quad >> 1) * 16;
    const uint32_t offB = (uint32_t)(wn * 64 + (quad & 1) * 8 + lr) * 80 + (quad >> 1) * 16;

    float acc[2][8][4];
    #pragma unroll
    for (int i = 0; i < 2; ++i)
        #pragma unroll
        for (int j = 0; j < 8; ++j)
            #pragma unroll
            for (int r = 0; r < 4; ++r) acc[i][j][r] = 0.f;

    auto load_stage = [&](int t) {
        const uint32_t sA = sbase + (t & (NSTG - 1)) * STAGEB;
        const uint32_t sB = sA + TILEB;
        const int k0 = t * 32;
        const __half* Ag = A + (size_t)(m0 + r_ld) * K + k0 + c_ld * 8;
        const __half* Wg = W + (size_t)(n0 + r_ld) * K + k0 + c_ld * 8;
        #pragma unroll
        for (int p = 0; p < 2; ++p) {
            cp_async16(sA + (p * 64 + r_ld) * (ROWH * 2) + c_ld * 16, Ag + (size_t)(p * 64) * K);
            cp_async16(sB + (p * 64 + r_ld) * (ROWH * 2) + c_ld * 16, Wg + (size_t)(p * 64) * K);
        }
    };

    #pragma unroll
    for (int t = 0; t < NSTG - 1; ++t) { load_stage(t); CP_COMMIT(); }

    for (int t = 0; t < NC; ++t) {
        CP_WAIT2();
        __syncthreads();
        if (t + NSTG - 1 < NC) load_stage(t + NSTG - 1);
        CP_COMMIT();

        const uint32_t fAb = sbase + (t & (NSTG - 1)) * STAGEB;
        const uint32_t fBb = fAb + TILEB;

        #pragma unroll
        for (int ks = 0; ks < 2; ++ks) {
            uint32_t a[2][4], bq[4][4];
            ldsm4(a[0], fAb + offA + ks * 32);
            ldsm4(a[1], fAb + offA + 16 * 80 + ks * 32);
            #pragma unroll
            for (int p = 0; p < 4; ++p)
                ldsm4(bq[p], fBb + offB + p * 16 * 80 + ks * 32);
            #pragma unroll
            for (int mt = 0; mt < 2; ++mt)
                #pragma unroll
                for (int p = 0; p < 4; ++p) {
                    mma_f16(acc[mt][2 * p],     a[mt][0], a[mt][1], a[mt][2], a[mt][3],
                            bq[p][0], bq[p][2]);
                    mma_f16(acc[mt][2 * p + 1], a[mt][0], a[mt][1], a[mt][2], a[mt][3],
                            bq[p][1], bq[p][3]);
                }
        }
    }
    CP_WAIT0();
    __syncthreads();

    // ---------------- epilogue: stage fp32 in smem (stride 133) ----------------
    float* stg = (float*)smem;
    #pragma unroll
    for (int mt = 0; mt < 2; ++mt) {
        #pragma unroll
        for (int nt = 0; nt < 8; ++nt) {
            const int row = wm * 32 + mt * 16 + g;
            const int col = wn * 64 + nt * 8 + t4 * 2;
            stg[row * 133 + col]           = acc[mt][nt][0];
            stg[row * 133 + col + 1]       = acc[mt][nt][1];
            stg[(row + 8) * 133 + col]     = acc[mt][nt][2];
            stg[(row + 8) * 133 + col + 1] = acc[mt][nt][3];
        }
    }
    __syncthreads();

    if (MODE == 0 || MODE == 1) {
        __half* Y = (__half*)Yv;
        const int rr = tid >> 1;
        const int cb = (tid & 1) * 64;
        __half* yp = Y + (size_t)(m0 + rr) * O + n0 + cb;
        const float* bp = bias + n0 + cb;
        #pragma unroll
        for (int i = 0; i < 8; ++i) {
            __half2 h[4];
            #pragma unroll
            for (int q = 0; q < 4; ++q) {
                float v0 = stg[rr * 133 + cb + i * 8 + q * 2]     + bp[i * 8 + q * 2];
                float v1 = stg[rr * 133 + cb + i * 8 + q * 2 + 1] + bp[i * 8 + q * 2 + 1];
                if (MODE == 1) { v0 = fmaxf(v0, 0.f); v1 = fmaxf(v1, 0.f); }
                h[q] = __floats2half2_rn(v0, v1);
            }
            *(uint4*)(yp + i * 8) = *(uint4*)h;
        }
    } else if (MODE == 2) {
        float* Y = (float*)Yv;
        const int bidx = m0 >> 12;
        const int npix = m0 & 4095;
        #pragma unroll
        for (int ci = 0; ci < 16; ++ci) {
            const int c = wid * 16 + ci;
            const int cg = n0 + c;
            const float bv = bias[cg];
            const size_t base = (((size_t)(bidx * 256 + cg)) << 12) + npix;
            #pragma unroll
            for (int i = 0; i < 4; ++i) {
                const int m = lane + 32 * i;
                Y[base + m] = stg[m * 133 + c] + bv + xres[base + m];
            }
        }
    } else {  // MODE 3: QKV
        if (n0 < 512) {
            // transposed q/k write: h_qkT[((qk*8+b)*4+h)*64+d][n], q scaled 1/8
            const int bidx = m0 >> 12;
            const int npix = m0 & 4095;
            #pragma unroll
            for (int ci = 0; ci < 16; ++ci) {
                const int c  = wid * 16 + ci;
                const int cg = n0 + c;
                const int qk = cg >> 8;
                const int hh = (cg >> 6) & 3;
                const int d  = cg & 63;
                const float sc = qk ? 1.f : 0.125f;
                const float bv = bias[cg];
                __half* rp = h_qkT + (((size_t)(((qk * 8 + bidx) * 4 + hh) * 64 + d)) << 12)
                           + npix + lane * 4;
                float v0 = (stg[(lane * 4 + 0) * 133 + c] + bv) * sc;
                float v1 = (stg[(lane * 4 + 1) * 133 + c] + bv) * sc;
                float v2 = (stg[(lane * 4 + 2) * 133 + c] + bv) * sc;
                float v3 = (stg[(lane * 4 + 3) * 133 + c] + bv) * sc;
                __half2 o[2] = { __floats2half2_rn(v0, v1), __floats2half2_rn(v2, v3) };
                *(uint2*)rp = *(uint2*)o;
            }
        } else {
            // v tile -> h_v normal layout
            const int rr = tid >> 1;
            const int cb = (tid & 1) * 64;
            __half* yp = h_v + (size_t)(m0 + rr) * 256 + (n0 - 512) + cb;
            const float* bp = bias + n0 + cb;
            #pragma unroll
            for (int i = 0; i < 8; ++i) {
                __half2 h[4];
                #pragma unroll
                for (int q = 0; q < 4; ++q) {
                    float v0 = stg[rr * 133 + cb + i * 8 + q * 2]     + bp[i * 8 + q * 2];
                    float v1 = stg[rr * 133 + cb + i * 8 + q * 2 + 1] + bp[i * 8 + q * 2 + 1];
                    h[q] = __floats2half2_rn(v0, v1);
                }
                *(uint4*)(yp + i * 8) = *(uint4*)h;
            }
        }
    }
}

// ---------------- attention S = qT . kT^T via mma (split-K) ----------------
__global__ __launch_bounds__(128) void attn_s_tc()
{
    const int bh = blockIdx.x, ch = blockIdx.y;
    const int b = bh >> 2, h = bh & 3;
    __shared__ __align__(16) __half sQ[2][64 * 40];
    __shared__ __align__(16) __half sK[2][64 * 40];
    const int tid = threadIdx.x, lane = tid & 31, w = tid >> 5;
    const uint32_t qb = smem_u32(sQ), kb = smem_u32(sK);
    const __half* qg = h_qkT + ((size_t)((b * 4 + h) * 64) << 12);
    const __half* kg = h_qkT + ((size_t)((32 + b * 4 + h) * 64) << 12);
    const int k0 = ch * 512;

    auto load = [&](int c) {
        const int buf = c & 1;
        const int kk = k0 + c * 32;
        #pragma unroll
        for (int j = 0; j < 2; ++j) {
            int idx = tid * 2 + j;
            int row = idx >> 2, c4 = idx & 3;
            cp_async16(qb + buf * 5120 + row * 80 + c4 * 16, qg + ((size_t)row << 12) + kk + c4 * 8);
            cp_async16(kb + buf * 5120 + row * 80 + c4 * 16, kg + ((size_t)row << 12) + kk + c4 * 8);
        }
    };

    float acc[8][4];
    #pragma unroll
    for (int j = 0; j < 8; ++j)
        #pragma unroll
        for (int r = 0; r < 4; ++r) acc[j][r] = 0.f;

    const int quad = lane >> 3, lr = lane & 7;
    const uint32_t offA = (uint32_t)(w * 16 + (quad & 1) * 8 + lr) * 80 + (quad >> 1) * 16;
    const uint32_t offB = (uint32_t)((quad & 1) * 8 + lr) * 80 + (quad >> 1) * 16;

    load(0); CP_COMMIT();
    for (int c = 0; c < 16; ++c) {
        CP_WAIT0();
        __syncthreads();
        if (c < 15) { load(c + 1); CP_COMMIT(); }
        const uint32_t qs = qb + (c & 1) * 5120;
        const uint32_t ks_ = kb + (c & 1) * 5120;
        #pragma unroll
        for (int kh = 0; kh < 2; ++kh) {
            uint32_t a[4], bq[4][4];
            ldsm4(a, qs + offA + kh * 32);
            #pragma unroll
            for (int p = 0; p < 4; ++p)
                ldsm4(bq[p], ks_ + offB + p * 16 * 80 + kh * 32);
            #pragma unroll
            for (int p = 0; p < 4; ++p) {
                mma_f16(acc[2 * p],     a[0], a[1], a[2], a[3], bq[p][0], bq[p][2]);
                mma_f16(acc[2 * p + 1], a[0], a[1], a[2], a[3], bq[p][1], bq[p][3]);
            }
        }
    }

    const int g = lane >> 2, t4 = lane & 3;
    float* sp = g_spart + (size_t)(bh * kNCH + ch) * 64 * 64;
    #pragma unroll
    for (int nt = 0; nt < 8; ++nt) {
        const int row = w * 16 + g, col = nt * 8 + t4 * 2;
        sp[row * 64 + col]           = acc[nt][0];
        sp[row * 64 + col + 1]       = acc[nt][1];
        sp[(row + 8) * 64 + col]     = acc[nt][2];
        sp[(row + 8) * 64 + col + 1] = acc[nt][3];
    }
}

// ---------------- softmax: reduce partials, emit fp16 rows [d][e] ----------------
__global__ __launch_bounds__(256) void softmax_kernel()
{
    int bh = blockIdx.x;
    int dd = blockIdx.y * 8 + (threadIdx.x >> 5);
    int lane = threadIdx.x & 31;
    const float* spb = g_spart + (size_t)bh * kNCH * 64 * 64 + dd * 64;
    float v0 = 0.f, v1 = 0.f;
    #pragma unroll
    for (int p = 0; p < kNCH; ++p) {
        v0 += spb[(size_t)p * 64 * 64 + lane];
        v1 += spb[(size_t)p * 64 * 64 + 32 + lane];
    }
    float m = fmaxf(v0, v1);
    #pragma unroll
    for (int off = 16; off; off >>= 1) m = fmaxf(m, __shfl_xor_sync(0xffffffffu, m, off));
    v0 = expf(v0 - m); v1 = expf(v1 - m);
    float s = v0 + v1;
    #pragma unroll
    for (int off = 16; off; off >>= 1) s += __shfl_xor_sync(0xffffffffu, s, off);
    float inv = 1.f / s;
    __half* at = h_attnw + (size_t)bh * 64 * 64 + dd * 64;
    at[lane]      = __float2half(v0 * inv);
    at[32 + lane] = __float2half(v1 * inv);
}

// ---------------- AV: out[n][d] = sum_e V[n][e] * attn[d][e], via mma ----------------
__global__ __launch_bounds__(128) void attn_av_tc()
{
    const int bh = blockIdx.y, b = bh >> 2, h = bh & 3;
    const int n0 = blockIdx.x * 128;
    __shared__ __align__(16) __half sV[128 * 72];
    __shared__ __align__(16) __half sA[64 * 72];
    const int tid = threadIdx.x, lane = tid & 31, w = tid >> 5;
    const uint32_t vb = smem_u32(sV), ab = smem_u32(sA);

    // load V tile (128 rows x 64 halves) and attn (64 x 64)
    #pragma unroll
    for (int j = 0; j < 8; ++j) {
        int idx = tid + j * 128;
        int row = idx >> 3, c8 = idx & 7;
        cp_async16(vb + row * 144 + c8 * 16,
                   h_v + ((size_t)(b * 4096 + n0 + row)) * 256 + h * 64 + c8 * 8);
    }
    #pragma unroll
    for (int j = 0; j < 4; ++j) {
        int idx = tid + j * 128;
        int row = idx >> 3, c8 = idx & 7;
        cp_async16(ab + row * 144 + c8 * 16,
                   h_attnw + (size_t)bh * 4096 + row * 64 + c8 * 8);
    }
    CP_COMMIT();
    CP_WAIT0();
    __syncthreads();

    const int quad = lane >> 3, lr = lane & 7;
    const uint32_t offA = (uint32_t)(w * 32 + (quad & 1) * 8 + lr) * 144 + (quad >> 1) * 16;
    const uint32_t offB = (uint32_t)((quad & 1) * 8 + lr) * 144 + (quad >> 1) * 16;

    float acc[2][8][4];
    #pragma unroll
    for (int i = 0; i < 2; ++i)
        #pragma unroll
        for (int j = 0; j < 8; ++j)
            #pragma unroll
            for (int r = 0; r < 4; ++r) acc[i][j][r] = 0.f;

    #pragma unroll
    for (int ks = 0; ks < 4; ++ks) {
        uint32_t a[2][4], bq[4][4];
        ldsm4(a[0], vb + offA + ks * 32);
        ldsm4(a[1], vb + offA + 16 * 144 + ks * 32);
        #pragma unroll
        for (int p = 0; p < 4; ++p)
            ldsm4(bq[p], ab + offB + p * 16 * 144 + ks * 32);
        #pragma unroll
        for (int mt = 0; mt < 2; ++mt)
            #pragma unroll
            for (int p = 0; p < 4; ++p) {
                mma_f16(acc[mt][2 * p],     a[mt][0], a[mt][1], a[mt][2], a[mt][3],
                        bq[p][0], bq[p][2]);
                mma_f16(acc[mt][2 * p + 1], a[mt][0], a[mt][1], a[mt][2], a[mt][3],
                        bq[p][1], bq[p][3]);
            }
    }

    const int g = lane >> 2, t4 = lane & 3;
    #pragma unroll
    for (int mt = 0; mt < 2; ++mt) {
        #pragma unroll
        for (int nt = 0; nt < 8; ++nt) {
            const int n1 = n0 + w * 32 + mt * 16 + g;
            const int d  = nt * 8 + t4 * 2;
            __half* yp = h_attnout + ((size_t)(b * 4096 + n1)) * 256 + h * 64 + d;
            *(__half2*)yp = __floats2half2_rn(acc[mt][nt][0], acc[mt][nt][1]);
            *(__half2*)(yp + 8 * 256) = __floats2half2_rn(acc[mt][nt][2], acc[mt][nt][3]);
        }
    }
}

// ---------------- LN2: h_proj -> h_ln2 ----------------
__global__ __launch_bounds__(256) void ln2_kernel(const float* __restrict__ g2,
                                                  const float* __restrict__ be2)
{
    int row  = blockIdx.x * 8 + (threadIdx.x >> 5);
    int lane = threadIdx.x & 31;
    const __half* p = h_proj + (size_t)row * kC + lane * 8;
    __half2 h[4];
    *(uint4*)h = *(const uint4*)p;
    float v[8];
    #pragma unroll
    for (int q = 0; q < 4; ++q) {
        float2 f = __half22float2(h[q]);
        v[q * 2] = f.x; v[q * 2 + 1] = f.y;
    }
    float s = 0.f, qq = 0.f;
    #pragma unroll
    for (int j = 0; j < 8; ++j) { s += v[j]; qq += v[j] * v[j]; }
    #pragma unroll
    for (int off = 16; off; off >>= 1) {
        s  += __shfl_xor_sync(0xffffffffu, s, off);
        qq += __shfl_xor_sync(0xffffffffu, qq, off);
    }
    float mu = s * (1.f / 256.f);
    float rs = rsqrtf(qq * (1.f / 256.f) - mu * mu + 1e-5f);
    const int c0 = lane * 8;
    __half2 o[4];
    #pragma unroll
    for (int q = 0; q < 4; ++q) {
        float o0 = (v[q * 2]     - mu) * rs * g2[c0 + q * 2]     + be2[c0 + q * 2];
        float o1 = (v[q * 2 + 1] - mu) * rs * g2[c0 + q * 2 + 1] + be2[c0 + q * 2 + 1];
        o[q] = __floats2half2_rn(o0, o1);
    }
    *(uint4*)(h_ln2 + (size_t)row * kC + c0) = *(uint4*)o;
}

// ---------------- launch ----------------
extern "C" void kernel_launch(void* const* d_in, const int* in_sizes, int n_in,
                              void* d_out, int out_size)
{
    const float* x      = (const float*)d_in[0];
    const float* w_qkv  = (const float*)d_in[1];
    const float* b_qkv  = (const float*)d_in[2];
    const float* w_proj = (const float*)d_in[3];
    const float* b_proj = (const float*)d_in[4];
    const float* w_ffn1 = (const float*)d_in[5];
    const float* b_ffn1 = (const float*)d_in[6];
    const float* w_ffn2 = (const float*)d_in[7];
    const float* b_ffn2 = (const float*)d_in[8];
    const float* g1     = (const float*)d_in[9];
    const float* be1    = (const float*)d_in[10];
    const float* g2     = (const float*)d_in[11];
    const float* be2    = (const float*)d_in[12];
    float* out = (float*)d_out;

    void *p_xln, *p_attnout, *p_proj, *p_ln2, *p_ffh, *p_w;
    cudaGetSymbolAddress(&p_xln, h_xln);
    cudaGetSymbolAddress(&p_attnout, h_attnout);
    cudaGetSymbolAddress(&p_proj, h_proj);
    cudaGetSymbolAddress(&p_ln2, h_ln2);
    cudaGetSymbolAddress(&p_ffh, h_ffh);
    cudaGetSymbolAddress(&p_w, h_w);
    const __half* hw = (const __half*)p_w;

    cudaFuncSetAttribute(gemm_h<0>, cudaFuncAttributeMaxDynamicSharedMemorySize, SMEM_DYN);
    cudaFuncSetAttribute(gemm_h<1>, cudaFuncAttributeMaxDynamicSharedMemorySize, SMEM_DYN);
    cudaFuncSetAttribute(gemm_h<2>, cudaFuncAttributeMaxDynamicSharedMemorySize, SMEM_DYN);
    cudaFuncSetAttribute(gemm_h<3>, cudaFuncAttributeMaxDynamicSharedMemorySize, SMEM_DYN);

    const int M = kB * kN;  // 32768

    convw_kernel<<<(OW_TOT + 255) / 256, 256>>>(w_qkv, w_proj, w_ffn1, w_ffn2);

    ln1_kernel<<<dim3(kN / 32, kB), 256>>>(x, g1, be1);

    // QKV: q,k -> h_qkT (transposed, q scaled); v -> h_v
    gemm_h<3><<<dim3(kC3 / 128, M / 128), 256, SMEM_DYN>>>(
        (const __half*)p_xln, hw + OW_QKV, b_qkv, nullptr, nullptr, kC, kC3);

    attn_s_tc<<<dim3(kBH, kNCH), 128>>>();
    softmax_kernel<<<dim3(kBH, 8), 256>>>();
    attn_av_tc<<<dim3(kN / 128, kBH), 128>>>();

    // proj
    gemm_h<0><<<dim3(kC / 128, M / 128), 256, SMEM_DYN>>>(
        (const __half*)p_attnout, hw + OW_PROJ, b_proj, p_proj, nullptr, kC, kC);

    ln2_kernel<<<M / 8, 256>>>(g2, be2);

    // FFN1 + ReLU
    gemm_h<1><<<dim3(kFFN / 128, M / 128), 256, SMEM_DYN>>>(
        (const __half*)p_ln2, hw + OW_FFN1, b_ffn1, p_ffh, nullptr, kC, kFFN);

    // FFN2 + residual + transpose
    gemm_h<2><<<dim3(kC / 128, M / 128), 256, SMEM_DYN>>>(
        (const __half*)p_ffh, hw + OW_FFN2, b_ffn2, out, x, kFFN, kC);
}

// round 6
// speedup vs baseline: 5.4388x; 1.1657x over previous
#include <cuda_runtime.h>
#include <cuda_fp16.h>
#include <cstdint>

// ---------------- problem constants ----------------
namespace {
constexpr int kB   = 8;
constexpr int kC   = 256;
constexpr int kN   = 4096;
constexpr int kC3  = 768;
constexpr int kFFN = 2048;
constexpr int kBH  = 32;
constexpr int kNCH = 8;

constexpr int ROWB   = 144;                 // padded row bytes for 64-halves K-chunk
constexpr int TILEB  = 128 * ROWB;          // 18432 bytes per operand tile
constexpr int STAGEB = 2 * TILEB;           // 36864
constexpr int NSTG   = 3;
constexpr uint32_t SMEM_DYN = STAGEB * NSTG; // 110592 (2 CTAs/SM: 221184 < 227KB)

constexpr int OW_QKV  = 0;
constexpr int OW_PROJ = OW_QKV + kC3 * kC;
constexpr int OW_FFN1 = OW_PROJ + kC * kC;
constexpr int OW_FFN2 = OW_FFN1 + kFFN * kC;
constexpr int OW_TOT  = OW_FFN2 + kC * kFFN;
}

// ---------------- scratch ----------------
__device__ __half h_xln[kB * kN * kC];
__device__ __half h_qkT[4096 * 4096];
__device__ __half h_v[kB * kN * kC];
__device__ float  g_spart[kBH * kNCH * 64 * 64];
__device__ __half h_attnw[kBH * 64 * 64];
__device__ __half h_attnout[kB * kN * kC];
__device__ __half h_proj[kB * kN * kC];
__device__ __half h_ln2[kB * kN * kC];
__device__ __half h_ffh[kB * kN * kFFN];
__device__ __half h_w[OW_TOT];

// ---------------- helpers ----------------
__device__ __forceinline__ uint32_t smem_u32(const void* p) {
    uint32_t a;
    asm("{ .reg .u64 t; cvta.to.shared.u64 t, %1; cvt.u32.u64 %0, t; }" : "=r"(a) : "l"(p));
    return a;
}
__device__ __forceinline__ void cp_async16(uint32_t s, const void* g) {
    asm volatile("cp.async.cg.shared.global [%0], [%1], 16;" :: "r"(s), "l"(g));
}
#define CP_COMMIT() asm volatile("cp.async.commit_group;" ::: "memory")
#define CP_WAIT1()  asm volatile("cp.async.wait_group 1;" ::: "memory")
#define CP_WAIT0()  asm volatile("cp.async.wait_group 0;" ::: "memory")

__device__ __forceinline__ void ldsm4(uint32_t* r, uint32_t a) {
    asm volatile("ldmatrix.sync.aligned.m8n8.x4.shared.b16 {%0,%1,%2,%3}, [%4];"
                 : "=r"(r[0]), "=r"(r[1]), "=r"(r[2]), "=r"(r[3]) : "r"(a));
}
__device__ __forceinline__ void stsm4(uint32_t a, const uint32_t* r) {
    asm volatile("stmatrix.sync.aligned.m8n8.x4.shared.b16 [%0], {%1,%2,%3,%4};"
                 :: "r"(a), "r"(r[0]), "r"(r[1]), "r"(r[2]), "r"(r[3]) : "memory");
}
__device__ __forceinline__ void mma_f16(float* c,
                                        uint32_t a0, uint32_t a1, uint32_t a2, uint32_t a3,
                                        uint32_t b0, uint32_t b1) {
    asm volatile(
        "mma.sync.aligned.m16n8k16.row.col.f32.f16.f16.f32 "
        "{%0,%1,%2,%3}, {%4,%5,%6,%7}, {%8,%9}, {%0,%1,%2,%3};"
        : "+f"(c[0]), "+f"(c[1]), "+f"(c[2]), "+f"(c[3])
        : "r"(a0), "r"(a1), "r"(a2), "r"(a3), "r"(b0), "r"(b1));
}
__device__ __forceinline__ uint32_t pack_h2(float x, float y) {
    __half2 h = __floats2half2_rn(x, y);
    return *(uint32_t*)&h;
}

// ---------------- weight conversion ----------------
__global__ __launch_bounds__(256) void convw_kernel(const float* __restrict__ wqkv,
                                                    const float* __restrict__ wproj,
                                                    const float* __restrict__ wffn1,
                                                    const float* __restrict__ wffn2)
{
    int i = blockIdx.x * 256 + threadIdx.x;
    if (i >= OW_TOT) return;
    float v;
    if (i < OW_PROJ)       v = wqkv[i - OW_QKV];
    else if (i < OW_FFN1)  v = wproj[i - OW_PROJ];
    else if (i < OW_FFN2)  v = wffn1[i - OW_FFN1];
    else                   v = wffn2[i - OW_FFN2];
    h_w[i] = __float2half(v);
}

// ---------------- LN1 ----------------
__global__ __launch_bounds__(256) void ln1_kernel(const float* __restrict__ x,
                                                  const float* __restrict__ g1,
                                                  const float* __restrict__ be1)
{
    __shared__ float s[32][257];
    __shared__ float smu[32], srs[32];
    int b  = blockIdx.y;
    int n0 = blockIdx.x * 32;
    int tid = threadIdx.x;
    const float* xb = x + (size_t)b * kC * kN;
    #pragma unroll
    for (int it = 0; it < 32; ++it) {
        int idx = it * 256 + tid;
        int c = idx >> 5, nn = idx & 31;
        s[nn][c] = xb[(size_t)c * kN + n0 + nn];
    }
    __syncthreads();
    int nn = tid >> 3, g = tid & 7;
    float sum = 0.f, sq = 0.f;
    #pragma unroll
    for (int j = 0; j < 32; ++j) { float v = s[nn][g + j * 8]; sum += v; sq += v * v; }
    sum += __shfl_xor_sync(0xffffffffu, sum, 1, 8);
    sum += __shfl_xor_sync(0xffffffffu, sum, 2, 8);
    sum += __shfl_xor_sync(0xffffffffu, sum, 4, 8);
    sq  += __shfl_xor_sync(0xffffffffu, sq, 1, 8);
    sq  += __shfl_xor_sync(0xffffffffu, sq, 2, 8);
    sq  += __shfl_xor_sync(0xffffffffu, sq, 4, 8);
    if (g == 0) {
        float mu = sum * (1.f / 256.f);
        smu[nn] = mu;
        srs[nn] = rsqrtf(sq * (1.f / 256.f) - mu * mu + 1e-5f);
    }
    __syncthreads();
    float gg = g1[tid], bb = be1[tid];
    __half* yb = h_xln + ((size_t)b * kN + n0) * kC;
    #pragma unroll
    for (int it = 0; it < 32; ++it)
        yb[(size_t)it * kC + tid] = __float2half((s[it][tid] - smu[it]) * srs[it] * gg + bb);
}

// ---------------- fp16 tensor GEMM 128x128x64, ldmatrix/stmatrix ----------------
// MODE 0: fp16 + bias.  MODE 1: fp16 + bias + ReLU.
// MODE 2: fp32 out (B,C,N), bias + residual + transpose.
// MODE 3: QKV: q/k transposed (q scaled 1/8) -> h_qkT; v -> h_v.
template <int MODE>
__global__ __launch_bounds__(256, 2) void gemm_h(const __half* __restrict__ A,
                                                 const __half* __restrict__ W,
                                                 const float* __restrict__ bias,
                                                 void* __restrict__ Yv,
                                                 const float* __restrict__ xres,
                                                 int K, int O)
{
    extern __shared__ __align__(16) char smem[];
    const uint32_t sbase = smem_u32(smem);
    const int tid = threadIdx.x;
    const int lane = tid & 31;
    const int wid = tid >> 5;
    const int g  = lane >> 2;
    const int t4 = lane & 3;
    const int wm = wid >> 1;
    const int wn = wid & 1;
    const int m0 = blockIdx.y * 128;
    const int n0 = blockIdx.x * 128;
    const int NC = K >> 6;

    const int r_ld = tid >> 3;     // 0..31 base row step
    const int c_ld = tid & 7;      // 16B chunk within 128B row

    const int quad = lane >> 3, lr = lane & 7;
    const uint32_t offA = (uint32_t)(wm * 32 + (quad & 1) * 8 + lr) * ROWB + (quad >> 1) * 16;
    const uint32_t offB = (uint32_t)(wn * 64 + (quad & 1) * 8 + lr) * ROWB + (quad >> 1) * 16;

    float acc[2][8][4];
    #pragma unroll
    for (int i = 0; i < 2; ++i)
        #pragma unroll
        for (int j = 0; j < 8; ++j)
            #pragma unroll
            for (int r = 0; r < 4; ++r) acc[i][j][r] = 0.f;

    auto load_stage = [&](int t) {
        const int bstg = t % NSTG;
        const uint32_t sA = sbase + bstg * STAGEB;
        const uint32_t sB = sA + TILEB;
        const int k0 = t * 64;
        const __half* Ag = A + (size_t)(m0 + r_ld) * K + k0 + c_ld * 8;
        const __half* Wg = W + (size_t)(n0 + r_ld) * K + k0 + c_ld * 8;
        #pragma unroll
        for (int p = 0; p < 4; ++p) {
            cp_async16(sA + (p * 32 + r_ld) * ROWB + c_ld * 16, Ag + (size_t)(p * 32) * K);
            cp_async16(sB + (p * 32 + r_ld) * ROWB + c_ld * 16, Wg + (size_t)(p * 32) * K);
        }
    };

    load_stage(0); CP_COMMIT();
    load_stage(1); CP_COMMIT();

    for (int t = 0; t < NC; ++t) {
        CP_WAIT1();
        __syncthreads();
        if (t + 2 < NC) { load_stage(t + 2); }
        CP_COMMIT();

        const uint32_t fAb = sbase + (t % NSTG) * STAGEB;
        const uint32_t fBb = fAb + TILEB;

        #pragma unroll
        for (int ks = 0; ks < 4; ++ks) {
            uint32_t a[2][4], bq[4][4];
            ldsm4(a[0], fAb + offA + ks * 32);
            ldsm4(a[1], fAb + offA + 16 * ROWB + ks * 32);
            #pragma unroll
            for (int p = 0; p < 4; ++p)
                ldsm4(bq[p], fBb + offB + p * 16 * ROWB + ks * 32);
            #pragma unroll
            for (int mt = 0; mt < 2; ++mt)
                #pragma unroll
                for (int p = 0; p < 4; ++p) {
                    mma_f16(acc[mt][2 * p],     a[mt][0], a[mt][1], a[mt][2], a[mt][3],
                            bq[p][0], bq[p][2]);
                    mma_f16(acc[mt][2 * p + 1], a[mt][0], a[mt][1], a[mt][2], a[mt][3],
                            bq[p][1], bq[p][3]);
                }
        }
    }
    CP_WAIT0();
    __syncthreads();

    if (MODE == 0 || MODE == 1) {
        // ---- fast fp16 epilogue: bias/relu in regs, stmatrix stage, uint4 out ----
        const uint32_t stg_b = sbase;
        float2 bv[8];
        #pragma unroll
        for (int nt = 0; nt < 8; ++nt)
            bv[nt] = *(const float2*)(bias + n0 + wn * 64 + nt * 8 + t4 * 2);
        const int q2 = lane >> 3, lr2 = lane & 7;
        #pragma unroll
        for (int mt = 0; mt < 2; ++mt) {
            #pragma unroll
            for (int np = 0; np < 4; ++np) {
                const int e0 = 2 * np, e1 = 2 * np + 1;
                float v0 = acc[mt][e0][0] + bv[e0].x, v1 = acc[mt][e0][1] + bv[e0].y;
                float v2 = acc[mt][e0][2] + bv[e0].x, v3 = acc[mt][e0][3] + bv[e0].y;
                float w0 = acc[mt][e1][0] + bv[e1].x, w1 = acc[mt][e1][1] + bv[e1].y;
                float w2 = acc[mt][e1][2] + bv[e1].x, w3 = acc[mt][e1][3] + bv[e1].y;
                if (MODE == 1) {
                    v0 = fmaxf(v0, 0.f); v1 = fmaxf(v1, 0.f);
                    v2 = fmaxf(v2, 0.f); v3 = fmaxf(v3, 0.f);
                    w0 = fmaxf(w0, 0.f); w1 = fmaxf(w1, 0.f);
                    w2 = fmaxf(w2, 0.f); w3 = fmaxf(w3, 0.f);
                }
                uint32_t r[4] = { pack_h2(v0, v1), pack_h2(v2, v3),
                                  pack_h2(w0, w1), pack_h2(w2, w3) };
                const uint32_t ad = stg_b
                    + (uint32_t)(wm * 32 + mt * 16 + (q2 & 1) * 8 + lr2) * 272
                    + (uint32_t)(wn * 64 + np * 16 + (q2 >> 1) * 8) * 2;
                stsm4(ad, r);
            }
        }
        __syncthreads();
        const __half* S = (const __half*)smem;
        __half* Y = (__half*)Yv;
        #pragma unroll
        for (int it = 0; it < 8; ++it) {
            const int id = tid + it * 256;
            const int row = id >> 4, seg = id & 15;
            *(uint4*)(Y + (size_t)(m0 + row) * O + n0 + seg * 8) =
                *(const uint4*)(S + row * 136 + seg * 8);
        }
        return;
    }

    // ---- fp32 staging epilogues (MODE 2/3) ----
    float* stg = (float*)smem;
    #pragma unroll
    for (int mt = 0; mt < 2; ++mt) {
        #pragma unroll
        for (int nt = 0; nt < 8; ++nt) {
            const int row = wm * 32 + mt * 16 + g;
            const int col = wn * 64 + nt * 8 + t4 * 2;
            stg[row * 133 + col]           = acc[mt][nt][0];
            stg[row * 133 + col + 1]       = acc[mt][nt][1];
            stg[(row + 8) * 133 + col]     = acc[mt][nt][2];
            stg[(row + 8) * 133 + col + 1] = acc[mt][nt][3];
        }
    }
    __syncthreads();

    if (MODE == 2) {
        float* Y = (float*)Yv;
        const int bidx = m0 >> 12;
        const int npix = m0 & 4095;
        #pragma unroll
        for (int ci = 0; ci < 16; ++ci) {
            const int c = wid * 16 + ci;
            const int cg = n0 + c;
            const float bv = bias[cg];
            const size_t base = (((size_t)(bidx * 256 + cg)) << 12) + npix;
            #pragma unroll
            for (int i = 0; i < 4; ++i) {
                const int m = lane + 32 * i;
                Y[base + m] = stg[m * 133 + c] + bv + xres[base + m];
            }
        }
    } else {  // MODE 3
        if (n0 < 512) {
            const int bidx = m0 >> 12;
            const int npix = m0 & 4095;
            #pragma unroll
            for (int ci = 0; ci < 16; ++ci) {
                const int c  = wid * 16 + ci;
                const int cg = n0 + c;
                const int qk = cg >> 8;
                const int hh = (cg >> 6) & 3;
                const int d  = cg & 63;
                const float sc = qk ? 1.f : 0.125f;
                const float bv = bias[cg];
                __half* rp = h_qkT + (((size_t)(((qk * 8 + bidx) * 4 + hh) * 64 + d)) << 12)
                           + npix + lane * 4;
                float v0 = (stg[(lane * 4 + 0) * 133 + c] + bv) * sc;
                float v1 = (stg[(lane * 4 + 1) * 133 + c] + bv) * sc;
                float v2 = (stg[(lane * 4 + 2) * 133 + c] + bv) * sc;
                float v3 = (stg[(lane * 4 + 3) * 133 + c] + bv) * sc;
                __half2 o[2] = { __floats2half2_rn(v0, v1), __floats2half2_rn(v2, v3) };
                *(uint2*)rp = *(uint2*)o;
            }
        } else {
            const int rr = tid >> 1;
            const int cb = (tid & 1) * 64;
            __half* yp = h_v + (size_t)(m0 + rr) * 256 + (n0 - 512) + cb;
            const float* bp = bias + n0 + cb;
            #pragma unroll
            for (int i = 0; i < 8; ++i) {
                __half2 h[4];
                #pragma unroll
                for (int q = 0; q < 4; ++q) {
                    float v0 = stg[rr * 133 + cb + i * 8 + q * 2]     + bp[i * 8 + q * 2];
                    float v1 = stg[rr * 133 + cb + i * 8 + q * 2 + 1] + bp[i * 8 + q * 2 + 1];
                    h[q] = __floats2half2_rn(v0, v1);
                }
                *(uint4*)(yp + i * 8) = *(uint4*)h;
            }
        }
    }
}

// ---------------- attention S = qT . kT^T via mma (split-K) ----------------
__global__ __launch_bounds__(128) void attn_s_tc()
{
    const int bh = blockIdx.x, ch = blockIdx.y;
    const int b = bh >> 2, h = bh & 3;
    __shared__ __align__(16) __half sQ[2][64 * 40];
    __shared__ __align__(16) __half sK[2][64 * 40];
    const int tid = threadIdx.x, lane = tid & 31, w = tid >> 5;
    const uint32_t qb = smem_u32(sQ), kb = smem_u32(sK);
    const __half* qg = h_qkT + ((size_t)((b * 4 + h) * 64) << 12);
    const __half* kg = h_qkT + ((size_t)((32 + b * 4 + h) * 64) << 12);
    const int k0 = ch * 512;

    auto load = [&](int c) {
        const int buf = c & 1;
        const int kk = k0 + c * 32;
        #pragma unroll
        for (int j = 0; j < 2; ++j) {
            int idx = tid * 2 + j;
            int row = idx >> 2, c4 = idx & 3;
            cp_async16(qb + buf * 5120 + row * 80 + c4 * 16, qg + ((size_t)row << 12) + kk + c4 * 8);
            cp_async16(kb + buf * 5120 + row * 80 + c4 * 16, kg + ((size_t)row << 12) + kk + c4 * 8);
        }
    };

    float acc[8][4];
    #pragma unroll
    for (int j = 0; j < 8; ++j)
        #pragma unroll
        for (int r = 0; r < 4; ++r) acc[j][r] = 0.f;

    const int quad = lane >> 3, lr = lane & 7;
    const uint32_t offA = (uint32_t)(w * 16 + (quad & 1) * 8 + lr) * 80 + (quad >> 1) * 16;
    const uint32_t offB = (uint32_t)((quad & 1) * 8 + lr) * 80 + (quad >> 1) * 16;

    load(0); CP_COMMIT();
    for (int c = 0; c < 16; ++c) {
        CP_WAIT0();
        __syncthreads();
        if (c < 15) { load(c + 1); CP_COMMIT(); }
        const uint32_t qs = qb + (c & 1) * 5120;
        const uint32_t ks_ = kb + (c & 1) * 5120;
        #pragma unroll
        for (int kh = 0; kh < 2; ++kh) {
            uint32_t a[4], bq[4][4];
            ldsm4(a, qs + offA + kh * 32);
            #pragma unroll
            for (int p = 0; p < 4; ++p)
                ldsm4(bq[p], ks_ + offB + p * 16 * 80 + kh * 32);
            #pragma unroll
            for (int p = 0; p < 4; ++p) {
                mma_f16(acc[2 * p],     a[0], a[1], a[2], a[3], bq[p][0], bq[p][2]);
                mma_f16(acc[2 * p + 1], a[0], a[1], a[2], a[3], bq[p][1], bq[p][3]);
            }
        }
    }

    const int g = lane >> 2, t4 = lane & 3;
    float* sp = g_spart + (size_t)(bh * kNCH + ch) * 64 * 64;
    #pragma unroll
    for (int nt = 0; nt < 8; ++nt) {
        const int row = w * 16 + g, col = nt * 8 + t4 * 2;
        sp[row * 64 + col]           = acc[nt][0];
        sp[row * 64 + col + 1]       = acc[nt][1];
        sp[(row + 8) * 64 + col]     = acc[nt][2];
        sp[(row + 8) * 64 + col + 1] = acc[nt][3];
    }
}

// ---------------- softmax ----------------
__global__ __launch_bounds__(256) void softmax_kernel()
{
    int bh = blockIdx.x;
    int dd = blockIdx.y * 8 + (threadIdx.x >> 5);
    int lane = threadIdx.x & 31;
    const float* spb = g_spart + (size_t)bh * kNCH * 64 * 64 + dd * 64;
    float v0 = 0.f, v1 = 0.f;
    #pragma unroll
    for (int p = 0; p < kNCH; ++p) {
        v0 += spb[(size_t)p * 64 * 64 + lane];
        v1 += spb[(size_t)p * 64 * 64 + 32 + lane];
    }
    float m = fmaxf(v0, v1);
    #pragma unroll
    for (int off = 16; off; off >>= 1) m = fmaxf(m, __shfl_xor_sync(0xffffffffu, m, off));
    v0 = expf(v0 - m); v1 = expf(v1 - m);
    float s = v0 + v1;
    #pragma unroll
    for (int off = 16; off; off >>= 1) s += __shfl_xor_sync(0xffffffffu, s, off);
    float inv = 1.f / s;
    __half* at = h_attnw + (size_t)bh * 64 * 64 + dd * 64;
    at[lane]      = __float2half(v0 * inv);
    at[32 + lane] = __float2half(v1 * inv);
}

// ---------------- AV ----------------
__global__ __launch_bounds__(128) void attn_av_tc()
{
    const int bh = blockIdx.y, b = bh >> 2, h = bh & 3;
    const int n0 = blockIdx.x * 128;
    __shared__ __align__(16) __half sV[128 * 72];
    __shared__ __align__(16) __half sA[64 * 72];
    const int tid = threadIdx.x, lane = tid & 31, w = tid >> 5;
    const uint32_t vb = smem_u32(sV), ab = smem_u32(sA);

    #pragma unroll
    for (int j = 0; j < 8; ++j) {
        int idx = tid + j * 128;
        int row = idx >> 3, c8 = idx & 7;
        cp_async16(vb + row * 144 + c8 * 16,
                   h_v + ((size_t)(b * 4096 + n0 + row)) * 256 + h * 64 + c8 * 8);
    }
    #pragma unroll
    for (int j = 0; j < 4; ++j) {
        int idx = tid + j * 128;
        int row = idx >> 3, c8 = idx & 7;
        cp_async16(ab + row * 144 + c8 * 16,
                   h_attnw + (size_t)bh * 4096 + row * 64 + c8 * 8);
    }
    CP_COMMIT();
    CP_WAIT0();
    __syncthreads();

    const int quad = lane >> 3, lr = lane & 7;
    const uint32_t offA = (uint32_t)(w * 32 + (quad & 1) * 8 + lr) * 144 + (quad >> 1) * 16;
    const uint32_t offB = (uint32_t)((quad & 1) * 8 + lr) * 144 + (quad >> 1) * 16;

    float acc[2][8][4];
    #pragma unroll
    for (int i = 0; i < 2; ++i)
        #pragma unroll
        for (int j = 0; j < 8; ++j)
            #pragma unroll
            for (int r = 0; r < 4; ++r) acc[i][j][r] = 0.f;

    #pragma unroll
    for (int ks = 0; ks < 4; ++ks) {
        uint32_t a[2][4], bq[4][4];
        ldsm4(a[0], vb + offA + ks * 32);
        ldsm4(a[1], vb + offA + 16 * 144 + ks * 32);
        #pragma unroll
        for (int p = 0; p < 4; ++p)
            ldsm4(bq[p], ab + offB + p * 16 * 144 + ks * 32);
        #pragma unroll
        for (int mt = 0; mt < 2; ++mt)
            #pragma unroll
            for (int p = 0; p < 4; ++p) {
                mma_f16(acc[mt][2 * p],     a[mt][0], a[mt][1], a[mt][2], a[mt][3],
                        bq[p][0], bq[p][2]);
                mma_f16(acc[mt][2 * p + 1], a[mt][0], a[mt][1], a[mt][2], a[mt][3],
                        bq[p][1], bq[p][3]);
            }
    }

    const int g = lane >> 2, t4 = lane & 3;
    #pragma unroll
    for (int mt = 0; mt < 2; ++mt) {
        #pragma unroll
        for (int nt = 0; nt < 8; ++nt) {
            const int n1 = n0 + w * 32 + mt * 16 + g;
            const int d  = nt * 8 + t4 * 2;
            __half* yp = h_attnout + ((size_t)(b * 4096 + n1)) * 256 + h * 64 + d;
            *(__half2*)yp = __floats2half2_rn(acc[mt][nt][0], acc[mt][nt][1]);
            *(__half2*)(yp + 8 * 256) = __floats2half2_rn(acc[mt][nt][2], acc[mt][nt][3]);
        }
    }
}

// ---------------- LN2 ----------------
__global__ __launch_bounds__(256) void ln2_kernel(const float* __restrict__ g2,
                                                  const float* __restrict__ be2)
{
    int row  = blockIdx.x * 8 + (threadIdx.x >> 5);
    int lane = threadIdx.x & 31;
    const __half* p = h_proj + (size_t)row * kC + lane * 8;
    __half2 h[4];
    *(uint4*)h = *(const uint4*)p;
    float v[8];
    #pragma unroll
    for (int q = 0; q < 4; ++q) {
        float2 f = __half22float2(h[q]);
        v[q * 2] = f.x; v[q * 2 + 1] = f.y;
    }
    float s = 0.f, qq = 0.f;
    #pragma unroll
    for (int j = 0; j < 8; ++j) { s += v[j]; qq += v[j] * v[j]; }
    #pragma unroll
    for (int off = 16; off; off >>= 1) {
        s  += __shfl_xor_sync(0xffffffffu, s, off);
        qq += __shfl_xor_sync(0xffffffffu, qq, off);
    }
    float mu = s * (1.f / 256.f);
    float rs = rsqrtf(qq * (1.f / 256.f) - mu * mu + 1e-5f);
    const int c0 = lane * 8;
    __half2 o[4];
    #pragma unroll
    for (int q = 0; q < 4; ++q) {
        float o0 = (v[q * 2]     - mu) * rs * g2[c0 + q * 2]     + be2[c0 + q * 2];
        float o1 = (v[q * 2 + 1] - mu) * rs * g2[c0 + q * 2 + 1] + be2[c0 + q * 2 + 1];
        o[q] = __floats2half2_rn(o0, o1);
    }
    *(uint4*)(h_ln2 + (size_t)row * kC + c0) = *(uint4*)o;
}

// ---------------- launch ----------------
extern "C" void kernel_launch(void* const* d_in, const int* in_sizes, int n_in,
                              void* d_out, int out_size)
{
    const float* x      = (const float*)d_in[0];
    const float* w_qkv  = (const float*)d_in[1];
    const float* b_qkv  = (const float*)d_in[2];
    const float* w_proj = (const float*)d_in[3];
    const float* b_proj = (const float*)d_in[4];
    const float* w_ffn1 = (const float*)d_in[5];
    const float* b_ffn1 = (const float*)d_in[6];
    const float* w_ffn2 = (const float*)d_in[7];
    const float* b_ffn2 = (const float*)d_in[8];
    const float* g1     = (const float*)d_in[9];
    const float* be1    = (const float*)d_in[10];
    const float* g2     = (const float*)d_in[11];
    const float* be2    = (const float*)d_in[12];
    float* out = (float*)d_out;

    void *p_xln, *p_attnout, *p_proj, *p_ln2, *p_ffh, *p_w;
    cudaGetSymbolAddress(&p_xln, h_xln);
    cudaGetSymbolAddress(&p_attnout, h_attnout);
    cudaGetSymbolAddress(&p_proj, h_proj);
    cudaGetSymbolAddress(&p_ln2, h_ln2);
    cudaGetSymbolAddress(&p_ffh, h_ffh);
    cudaGetSymbolAddress(&p_w, h_w);
    const __half* hw = (const __half*)p_w;

    cudaFuncSetAttribute(gemm_h<0>, cudaFuncAttributeMaxDynamicSharedMemorySize, SMEM_DYN);
    cudaFuncSetAttribute(gemm_h<1>, cudaFuncAttributeMaxDynamicSharedMemorySize, SMEM_DYN);
    cudaFuncSetAttribute(gemm_h<2>, cudaFuncAttributeMaxDynamicSharedMemorySize, SMEM_DYN);
    cudaFuncSetAttribute(gemm_h<3>, cudaFuncAttributeMaxDynamicSharedMemorySize, SMEM_DYN);

    const int M = kB * kN;  // 32768

    convw_kernel<<<(OW_TOT + 255) / 256, 256>>>(w_qkv, w_proj, w_ffn1, w_ffn2);

    ln1_kernel<<<dim3(kN / 32, kB), 256>>>(x, g1, be1);

    gemm_h<3><<<dim3(kC3 / 128, M / 128), 256, SMEM_DYN>>>(
        (const __half*)p_xln, hw + OW_QKV, b_qkv, nullptr, nullptr, kC, kC3);

    attn_s_tc<<<dim3(kBH, kNCH), 128>>>();
    softmax_kernel<<<dim3(kBH, 8), 256>>>();
    attn_av_tc<<<dim3(kN / 128, kBH), 128>>>();

    gemm_h<0><<<dim3(kC / 128, M / 128), 256, SMEM_DYN>>>(
        (const __half*)p_attnout, hw + OW_PROJ, b_proj, p_proj, nullptr, kC, kC);

    ln2_kernel<<<M / 8, 256>>>(g2, be2);

    gemm_h<1><<<dim3(kFFN / 128, M / 128), 256, SMEM_DYN>>>(
        (const __half*)p_ln2, hw + OW_FFN1, b_ffn1, p_ffh, nullptr, kC, kFFN);

    gemm_h<2><<<dim3(kC / 128, M / 128), 256, SMEM_DYN>>>(
        (const __half*)p_ffh, hw + OW_FFN2, b_ffn2, out, x, kFFN, kC);
}